// round 9
// baseline (speedup 1.0000x reference)
#include <cuda_runtime.h>
#include <cuda_bf16.h>
#include <cstdint>

#define BH     64
#define SEQ    8192
#define DIM    64
#define NCHUNK 32
#define CHUNK  (SEQ / NCHUNK)   // 256
#define TS     16
#define NT     (CHUNK / TS)     // 16
#define HPG    32               // heads per pipeline group
#define GROUPS (BH / HPG)       // 2

typedef unsigned long long u64;

// Scratch (allocation-free: __device__ globals)
__device__ float g_kv_part[BH * NCHUNK * DIM * DIM];  // 32 MB
__device__ float g_ks_part[BH * NCHUNK * DIM];
__device__ float g_kvT[BH * 72 * DIM];                // [e(64)+ksum(1)+pad(7)][d(64)]

// ---- packed f32x2 helpers ---------------------------------------------------
__device__ __forceinline__ u64 pack2(float lo, float hi) {
    u64 r;
    asm("mov.b64 %0, {%1, %2};" : "=l"(r) : "f"(lo), "f"(hi));
    return r;
}
__device__ __forceinline__ void unpack2(u64 v, float& lo, float& hi) {
    asm("mov.b64 {%0, %1}, %2;" : "=f"(lo), "=f"(hi) : "l"(v));
}
__device__ __forceinline__ void fma2(u64& d, u64 a, u64 b) {
    asm("fma.rn.f32x2 %0, %1, %2, %0;" : "+l"(d) : "l"(a), "l"(b));
}
// ---- cp.async helpers --------------------------------------------------------
__device__ __forceinline__ void cp16(void* s, const void* g) {
    uint32_t sa = (uint32_t)__cvta_generic_to_shared(s);
    asm volatile("cp.async.cg.shared.global [%0], [%1], 16;"
                 :: "r"(sa), "l"(g) : "memory");
}
#define CP_COMMIT() asm volatile("cp.async.commit_group;" ::: "memory")
#define CP_WAIT1()  asm volatile("cp.async.wait_group 1;" ::: "memory")

// ---------------------------------------------------------------------------
// Phase 1 (proven config, head-offset): partial kv = relu(K)^T @ V, ksum.
// ---------------------------------------------------------------------------
__global__ __launch_bounds__(64) void la_phase1(const float* __restrict__ K,
                                                const float* __restrict__ V,
                                                int bh0) {
    const int bh = bh0 + blockIdx.x, chunk = blockIdx.y;
    const float* Kh = K + (size_t)bh * SEQ * DIM + (size_t)chunk * CHUNK * DIM;
    const float* Vh = V + (size_t)bh * SEQ * DIM + (size_t)chunk * CHUNK * DIM;

    __shared__ float Ks[2][TS][DIM];
    __shared__ float Vs[2][TS][DIM];

    const int t  = threadIdx.x;
    const int tx = t & 7;
    const int ty = t >> 3;

    int crow[4], ccol[4];
#pragma unroll
    for (int l = 0; l < 4; l++) {
        int idx = l * 64 + t;
        crow[l] = idx >> 4;
        ccol[l] = (idx & 15) * 4;
    }

    u64 acc[8][4];
    float ksum[8];
#pragma unroll
    for (int i = 0; i < 8; i++) {
        ksum[i] = 0.f;
#pragma unroll
        for (int j = 0; j < 4; j++) acc[i][j] = 0ull;
    }

#pragma unroll
    for (int p = 0; p < 2; p++) {
#pragma unroll
        for (int l = 0; l < 4; l++) {
            cp16(&Ks[p][crow[l]][ccol[l]],
                 Kh + (size_t)(p * TS + crow[l]) * DIM + ccol[l]);
            cp16(&Vs[p][crow[l]][ccol[l]],
                 Vh + (size_t)(p * TS + crow[l]) * DIM + ccol[l]);
        }
        CP_COMMIT();
    }

    for (int tl = 0; tl < NT; tl++) {
        CP_WAIT1();
        __syncthreads();
        const int b = tl & 1;

#pragma unroll 8
        for (int s = 0; s < TS; s++) {
            float4 ka = *(const float4*)&Ks[b][s][ty * 8];
            float4 kb = *(const float4*)&Ks[b][s][ty * 8 + 4];
            ulonglong2 va = *(const ulonglong2*)&Vs[b][s][tx * 8];
            ulonglong2 vb = *(const ulonglong2*)&Vs[b][s][tx * 8 + 4];
            float kf[8] = {ka.x, ka.y, ka.z, ka.w, kb.x, kb.y, kb.z, kb.w};
#pragma unroll
            for (int i = 0; i < 8; i++) {
                float km = fmaxf(kf[i], 0.f);
                ksum[i] += km;
                u64 k2 = pack2(km, km);
                fma2(acc[i][0], k2, va.x);
                fma2(acc[i][1], k2, va.y);
                fma2(acc[i][2], k2, vb.x);
                fma2(acc[i][3], k2, vb.y);
            }
        }
        __syncthreads();

        if (tl + 2 < NT) {
#pragma unroll
            for (int l = 0; l < 4; l++) {
                cp16(&Ks[b][crow[l]][ccol[l]],
                     Kh + (size_t)((tl + 2) * TS + crow[l]) * DIM + ccol[l]);
                cp16(&Vs[b][crow[l]][ccol[l]],
                     Vh + (size_t)((tl + 2) * TS + crow[l]) * DIM + ccol[l]);
            }
        }
        CP_COMMIT();
    }

    float* kvp = g_kv_part + ((size_t)bh * NCHUNK + chunk) * DIM * DIM;
#pragma unroll
    for (int i = 0; i < 8; i++) {
        int d = ty * 8 + i;
        float o0, o1, o2, o3, o4, o5, o6, o7;
        unpack2(acc[i][0], o0, o1);
        unpack2(acc[i][1], o2, o3);
        unpack2(acc[i][2], o4, o5);
        unpack2(acc[i][3], o6, o7);
        *(float4*)&kvp[d * DIM + tx * 8]     = make_float4(o0, o1, o2, o3);
        *(float4*)&kvp[d * DIM + tx * 8 + 4] = make_float4(o4, o5, o6, o7);
    }
    if (tx == 0) {
#pragma unroll
        for (int i = 0; i < 8; i++)
            g_ks_part[((size_t)bh * NCHUNK + chunk) * DIM + ty * 8 + i] = ksum[i];
    }
}

// ---------------------------------------------------------------------------
// Reduce partials -> g_kvT[bh][72][64] (kv^T, ksum row 64, zero pad 65-71)
// ---------------------------------------------------------------------------
__global__ __launch_bounds__(256) void la_reduce(int bh0) {
    const int bh  = bh0 + blockIdx.x;
    const int tid = threadIdx.x;
    float* outT = g_kvT + (size_t)bh * 72 * DIM;
    for (int idx = tid; idx < DIM * DIM; idx += 256) {
        int d = idx >> 6, e = idx & 63;
        float sum = 0.f;
#pragma unroll
        for (int c = 0; c < NCHUNK; c++)
            sum += g_kv_part[((size_t)bh * NCHUNK + c) * DIM * DIM + idx];
        outT[e * DIM + d] = sum;
    }
    if (tid < DIM) {
        float s = 0.f;
#pragma unroll
        for (int c = 0; c < NCHUNK; c++)
            s += g_ks_part[((size_t)bh * NCHUNK + c) * DIM + tid];
        outT[64 * DIM + tid] = s;
    }
    for (int i = tid; i < 7 * DIM; i += 256)
        outT[65 * DIM + i] = 0.f;
}

// ===========================================================================
// Phase 2 (R5-proven, head-offset): mma.sync bf16, 3-term split, dedup smem.
// 256 threads, warp w owns m-tile rows w*16..+15; 9 n-tiles, 12 k-steps.
// ===========================================================================
#define KPAD2 136
#define A_BYTES (128 * KPAD2 * 2)   // 34816
#define B_BYTES (72 * KPAD2 * 2)    // 19584
#define P2_SMEM (A_BYTES + B_BYTES) // 54400

__device__ __forceinline__ uint32_t pack_bf2(__nv_bfloat16 lo, __nv_bfloat16 hi) {
    __nv_bfloat162 t = __halves2bfloat162(lo, hi);
    return *(uint32_t*)&t;
}

__global__ __launch_bounds__(256) void la_phase2(const float* __restrict__ Q,
                                                 float* __restrict__ O,
                                                 int bh0) {
    extern __shared__ char sm[];
    __nv_bfloat16* As = (__nv_bfloat16*)sm;
    __nv_bfloat16* Bs = (__nv_bfloat16*)(sm + A_BYTES);

    const int bh = bh0 + blockIdx.x;
    const int rb = blockIdx.y;
    const float* Qh = Q + (size_t)bh * SEQ * DIM + (size_t)rb * 128 * DIM;

    const int tid  = threadIdx.x;
    const int lane = tid & 31;
    const int wid  = tid >> 5;

    // ---- stage A = relu(Q) [hi|lo]: 2048 float4 / 256 thr = 8 each ----
#pragma unroll
    for (int l = 0; l < 8; l++) {
        int idx = l * 256 + tid;
        int m = idx >> 4;
        int k = (idx & 15) * 4;
        float4 q = *(const float4*)(Qh + (size_t)m * DIM + k);
        q.x = fmaxf(q.x, 0.f); q.y = fmaxf(q.y, 0.f);
        q.z = fmaxf(q.z, 0.f); q.w = fmaxf(q.w, 0.f);
        __nv_bfloat16 hx = __float2bfloat16_rn(q.x), hy = __float2bfloat16_rn(q.y);
        __nv_bfloat16 hz = __float2bfloat16_rn(q.z), hw = __float2bfloat16_rn(q.w);
        __nv_bfloat16 lx = __float2bfloat16_rn(q.x - __bfloat162float(hx));
        __nv_bfloat16 ly = __float2bfloat16_rn(q.y - __bfloat162float(hy));
        __nv_bfloat16 lz = __float2bfloat16_rn(q.z - __bfloat162float(hz));
        __nv_bfloat16 lw = __float2bfloat16_rn(q.w - __bfloat162float(hw));
        __nv_bfloat16* row = As + (size_t)m * KPAD2;
        *(uint2*)(row + k)      = make_uint2(pack_bf2(hx, hy), pack_bf2(hz, hw));
        *(uint2*)(row + 64 + k) = make_uint2(pack_bf2(lx, ly), pack_bf2(lz, lw));
    }
    // ---- stage B = g_kvT [hi|lo] ----
    const float* Bg = g_kvT + (size_t)bh * 72 * DIM;
    for (int idx = tid; idx < 72 * 16; idx += 256) {
        int n = idx >> 4;
        int k = (idx & 15) * 4;
        float4 b = *(const float4*)(Bg + (size_t)n * DIM + k);
        __nv_bfloat16 hx = __float2bfloat16_rn(b.x), hy = __float2bfloat16_rn(b.y);
        __nv_bfloat16 hz = __float2bfloat16_rn(b.z), hw = __float2bfloat16_rn(b.w);
        __nv_bfloat16 lx = __float2bfloat16_rn(b.x - __bfloat162float(hx));
        __nv_bfloat16 ly = __float2bfloat16_rn(b.y - __bfloat162float(hy));
        __nv_bfloat16 lz = __float2bfloat16_rn(b.z - __bfloat162float(hz));
        __nv_bfloat16 lw = __float2bfloat16_rn(b.w - __bfloat162float(hw));
        __nv_bfloat16* row = Bs + (size_t)n * KPAD2;
        *(uint2*)(row + k)      = make_uint2(pack_bf2(hx, hy), pack_bf2(hz, hw));
        *(uint2*)(row + 64 + k) = make_uint2(pack_bf2(lx, ly), pack_bf2(lz, lw));
    }
    __syncthreads();

    // ---- mainloop ----
    const int m0 = wid * 16;
    uint32_t Abase = (uint32_t)__cvta_generic_to_shared(As);
    uint32_t Bbase = (uint32_t)__cvta_generic_to_shared(Bs);
    uint32_t aAddr = Abase + (uint32_t)(m0 + (lane & 15)) * (KPAD2 * 2)
                   + (uint32_t)(lane >> 4) * 16;
    uint32_t bAddr = Bbase + (uint32_t)(lane & 7) * (KPAD2 * 2)
                   + (uint32_t)((lane >> 3) & 1) * 16;

    constexpr int aOffs[12] = {0,32,64,96, 0,32,64,96, 128,160,192,224};
    constexpr int bOffs[12] = {0,32,64,96, 128,160,192,224, 0,32,64,96};

    float acc[9][4];
#pragma unroll
    for (int j = 0; j < 9; j++)
#pragma unroll
        for (int r = 0; r < 4; r++) acc[j][r] = 0.f;

#pragma unroll
    for (int ks = 0; ks < 12; ks++) {
        uint32_t a0, a1, a2, a3;
        asm volatile("ldmatrix.sync.aligned.m8n8.x4.shared.b16 {%0,%1,%2,%3}, [%4];"
                     : "=r"(a0), "=r"(a1), "=r"(a2), "=r"(a3)
                     : "r"(aAddr + aOffs[ks]));
#pragma unroll
        for (int j = 0; j < 9; j++) {
            uint32_t b0, b1;
            asm volatile("ldmatrix.sync.aligned.m8n8.x2.shared.b16 {%0,%1}, [%2];"
                         : "=r"(b0), "=r"(b1)
                         : "r"(bAddr + j * (8 * KPAD2 * 2) + bOffs[ks]));
            asm volatile(
                "mma.sync.aligned.m16n8k16.row.col.f32.bf16.bf16.f32 "
                "{%0,%1,%2,%3}, {%4,%5,%6,%7}, {%8,%9}, {%0,%1,%2,%3};"
                : "+f"(acc[j][0]), "+f"(acc[j][1]), "+f"(acc[j][2]), "+f"(acc[j][3])
                : "r"(a0), "r"(a1), "r"(a2), "r"(a3), "r"(b0), "r"(b1));
        }
    }

    // ---- epilogue ----
    const int g = lane >> 2;
    float nlo = __shfl_sync(0xffffffffu, acc[8][0], lane & ~3);
    float nhi = __shfl_sync(0xffffffffu, acc[8][2], lane & ~3);
    float ilo = 1.f / fmaxf(nlo, 1e-6f);
    float ihi = 1.f / fmaxf(nhi, 1e-6f);

    float* O0 = O + ((size_t)bh * SEQ + (size_t)rb * 128 + m0 + g) * DIM + 2 * (lane & 3);
    float* O1 = O0 + 8 * DIM;
#pragma unroll
    for (int j = 0; j < 8; j++) {
        *(float2*)(O0 + j * 8) = make_float2(acc[j][0] * ilo, acc[j][1] * ilo);
        *(float2*)(O1 + j * 8) = make_float2(acc[j][2] * ihi, acc[j][3] * ihi);
    }
}

// ---------------------------------------------------------------------------
// Launch: 2-way head pipeline. Half-grids stay large (1024-2048 CTAs), so
// phase1 keeps its occupancy while phase2 of the previous half overlaps on
// the tensor pipe. Capture-legal fork/join via events.
// ---------------------------------------------------------------------------
extern "C" void kernel_launch(void* const* d_in, const int* in_sizes, int n_in,
                              void* d_out, int out_size) {
    const float* q = (const float*)d_in[0];
    const float* k = (const float*)d_in[1];
    const float* v = (const float*)d_in[2];
    float* o = (float*)d_out;

    static bool inited = false;
    static cudaStream_t s1, s2;
    static cudaEvent_t evFork, evJ1, evJ2, evG[GROUPS];
    if (!inited) {
        cudaStreamCreateWithFlags(&s1, cudaStreamNonBlocking);
        cudaStreamCreateWithFlags(&s2, cudaStreamNonBlocking);
        cudaEventCreateWithFlags(&evFork, cudaEventDisableTiming);
        cudaEventCreateWithFlags(&evJ1, cudaEventDisableTiming);
        cudaEventCreateWithFlags(&evJ2, cudaEventDisableTiming);
        for (int g = 0; g < GROUPS; g++)
            cudaEventCreateWithFlags(&evG[g], cudaEventDisableTiming);
        cudaFuncSetAttribute(la_phase2, cudaFuncAttributeMaxDynamicSharedMemorySize,
                             P2_SMEM);
        inited = true;
    }

    cudaEventRecord(evFork, 0);
    cudaStreamWaitEvent(s1, evFork, 0);
    cudaStreamWaitEvent(s2, evFork, 0);

    for (int g = 0; g < GROUPS; g++) {
        const int bh0 = g * HPG;
        la_phase1<<<dim3(HPG, NCHUNK), 64, 0, s1>>>(k, v, bh0);
        la_reduce<<<HPG, 256, 0, s1>>>(bh0);
        cudaEventRecord(evG[g], s1);
        cudaStreamWaitEvent(s2, evG[g], 0);
        la_phase2<<<dim3(HPG, SEQ / 128), 256, P2_SMEM, s2>>>(q, o, bh0);
    }

    cudaEventRecord(evJ1, s1);
    cudaEventRecord(evJ2, s2);
    cudaStreamWaitEvent(0, evJ1, 0);
    cudaStreamWaitEvent(0, evJ2, 0);
}

// round 10
// speedup vs baseline: 1.0196x; 1.0196x over previous
#include <cuda_runtime.h>
#include <cuda_bf16.h>
#include <cstdint>

#define BH     64
#define SEQ    8192
#define DIM    64
#define NCHUNK 32
#define CHUNK  (SEQ / NCHUNK)   // 256
#define TS     16
#define NT     (CHUNK / TS)     // 16

typedef unsigned long long u64;

// Scratch (allocation-free: __device__ globals)
__device__ float g_kv_part[BH * NCHUNK * DIM * DIM];  // 32 MB
__device__ float g_ks_part[BH * NCHUNK * DIM];
__device__ float g_kvT[BH * 72 * DIM];   // tensor B: [e64+ksum+pad7][d64]
__device__ float g_kv [BH * DIM * DIM];  // fma path: [d][e]
__device__ float g_ks [BH * DIM];

// ---- packed f32x2 helpers ---------------------------------------------------
__device__ __forceinline__ u64 pack2(float lo, float hi) {
    u64 r;
    asm("mov.b64 %0, {%1, %2};" : "=l"(r) : "f"(lo), "f"(hi));
    return r;
}
__device__ __forceinline__ void unpack2(u64 v, float& lo, float& hi) {
    asm("mov.b64 {%0, %1}, %2;" : "=f"(lo), "=f"(hi) : "l"(v));
}
__device__ __forceinline__ void fma2(u64& d, u64 a, u64 b) {
    asm("fma.rn.f32x2 %0, %1, %2, %0;" : "+l"(d) : "l"(a), "l"(b));
}
// ---- cp.async helpers --------------------------------------------------------
__device__ __forceinline__ void cp16(void* s, const void* g) {
    uint32_t sa = (uint32_t)__cvta_generic_to_shared(s);
    asm volatile("cp.async.cg.shared.global [%0], [%1], 16;"
                 :: "r"(sa), "l"(g) : "memory");
}
#define CP_COMMIT() asm volatile("cp.async.commit_group;" ::: "memory")
#define CP_WAIT1()  asm volatile("cp.async.wait_group 1;" ::: "memory")

// swizzled column for fma-path kv smem
__device__ __forceinline__ int swz(int e) { return e + ((e >> 5) << 2); }

// ---------------------------------------------------------------------------
// Phase 1 (unchanged, measured best): partial kv = relu(K)^T @ V, ksum.
// ---------------------------------------------------------------------------
__global__ __launch_bounds__(64) void la_phase1(const float* __restrict__ K,
                                                const float* __restrict__ V) {
    const int bh = blockIdx.x, chunk = blockIdx.y;
    const float* Kh = K + (size_t)bh * SEQ * DIM + (size_t)chunk * CHUNK * DIM;
    const float* Vh = V + (size_t)bh * SEQ * DIM + (size_t)chunk * CHUNK * DIM;

    __shared__ float Ks[2][TS][DIM];
    __shared__ float Vs[2][TS][DIM];

    const int t  = threadIdx.x;
    const int tx = t & 7;
    const int ty = t >> 3;

    int crow[4], ccol[4];
#pragma unroll
    for (int l = 0; l < 4; l++) {
        int idx = l * 64 + t;
        crow[l] = idx >> 4;
        ccol[l] = (idx & 15) * 4;
    }

    u64 acc[8][4];
    float ksum[8];
#pragma unroll
    for (int i = 0; i < 8; i++) {
        ksum[i] = 0.f;
#pragma unroll
        for (int j = 0; j < 4; j++) acc[i][j] = 0ull;
    }

#pragma unroll
    for (int p = 0; p < 2; p++) {
#pragma unroll
        for (int l = 0; l < 4; l++) {
            cp16(&Ks[p][crow[l]][ccol[l]],
                 Kh + (size_t)(p * TS + crow[l]) * DIM + ccol[l]);
            cp16(&Vs[p][crow[l]][ccol[l]],
                 Vh + (size_t)(p * TS + crow[l]) * DIM + ccol[l]);
        }
        CP_COMMIT();
    }

    for (int tl = 0; tl < NT; tl++) {
        CP_WAIT1();
        __syncthreads();
        const int b = tl & 1;

#pragma unroll 8
        for (int s = 0; s < TS; s++) {
            float4 ka = *(const float4*)&Ks[b][s][ty * 8];
            float4 kb = *(const float4*)&Ks[b][s][ty * 8 + 4];
            ulonglong2 va = *(const ulonglong2*)&Vs[b][s][tx * 8];
            ulonglong2 vb = *(const ulonglong2*)&Vs[b][s][tx * 8 + 4];
            float kf[8] = {ka.x, ka.y, ka.z, ka.w, kb.x, kb.y, kb.z, kb.w};
#pragma unroll
            for (int i = 0; i < 8; i++) {
                float km = fmaxf(kf[i], 0.f);
                ksum[i] += km;
                u64 k2 = pack2(km, km);
                fma2(acc[i][0], k2, va.x);
                fma2(acc[i][1], k2, va.y);
                fma2(acc[i][2], k2, vb.x);
                fma2(acc[i][3], k2, vb.y);
            }
        }
        __syncthreads();

        if (tl + 2 < NT) {
#pragma unroll
            for (int l = 0; l < 4; l++) {
                cp16(&Ks[b][crow[l]][ccol[l]],
                     Kh + (size_t)((tl + 2) * TS + crow[l]) * DIM + ccol[l]);
                cp16(&Vs[b][crow[l]][ccol[l]],
                     Vh + (size_t)((tl + 2) * TS + crow[l]) * DIM + ccol[l]);
            }
        }
        CP_COMMIT();
    }

    float* kvp = g_kv_part + ((size_t)bh * NCHUNK + chunk) * DIM * DIM;
#pragma unroll
    for (int i = 0; i < 8; i++) {
        int d = ty * 8 + i;
        float o0, o1, o2, o3, o4, o5, o6, o7;
        unpack2(acc[i][0], o0, o1);
        unpack2(acc[i][1], o2, o3);
        unpack2(acc[i][2], o4, o5);
        unpack2(acc[i][3], o6, o7);
        *(float4*)&kvp[d * DIM + tx * 8]     = make_float4(o0, o1, o2, o3);
        *(float4*)&kvp[d * DIM + tx * 8 + 4] = make_float4(o4, o5, o6, o7);
    }
    if (tx == 0) {
#pragma unroll
        for (int i = 0; i < 8; i++)
            g_ks_part[((size_t)bh * NCHUNK + chunk) * DIM + ty * 8 + i] = ksum[i];
    }
}

// ---------------------------------------------------------------------------
// Reduce partials -> g_kvT (tensor layout), g_kv ([d][e]), g_ks
// ---------------------------------------------------------------------------
__global__ __launch_bounds__(256) void la_reduce() {
    const int bh  = blockIdx.x;
    const int tid = threadIdx.x;
    float* outT = g_kvT + (size_t)bh * 72 * DIM;
    float* outN = g_kv  + (size_t)bh * DIM * DIM;
    for (int idx = tid; idx < DIM * DIM; idx += 256) {
        int d = idx >> 6, e = idx & 63;
        float sum = 0.f;
#pragma unroll
        for (int c = 0; c < NCHUNK; c++)
            sum += g_kv_part[((size_t)bh * NCHUNK + c) * DIM * DIM + idx];
        outT[e * DIM + d] = sum;
        outN[idx] = sum;
    }
    if (tid < DIM) {
        float s = 0.f;
#pragma unroll
        for (int c = 0; c < NCHUNK; c++)
            s += g_ks_part[((size_t)bh * NCHUNK + c) * DIM + tid];
        outT[64 * DIM + tid] = s;
        g_ks[bh * DIM + tid] = s;
    }
    for (int i = tid; i < 7 * DIM; i += 256)
        outT[65 * DIM + i] = 0.f;
}

// ===========================================================================
// Phase 2 GRID-HYBRID: one kernel, 256 threads, 128 rows per CTA.
// blockIdx.y % 5 < 3  -> TENSOR engine (R5 HMMA path, tensor pipe)   [39/64]
// else                -> FMA engine (R2 f32x2 path, fma pipe)        [25/64]
// Both engines co-reside per SM; disjoint pipes overlap.
// ===========================================================================
#define KPAD2 136
#define A_BYTES (128 * KPAD2 * 2)   // 34816
#define B_BYTES (72 * KPAD2 * 2)    // 19584
#define P2_SMEM (A_BYTES + B_BYTES) // 54400
// fma-path smem union layout (fits inside P2_SMEM):
#define F_KV  0                     // [64][68] f32  = 17408
#define F_QS  17408                 // [128][36] f32 = 18432
#define F_KS  35840                 // [130] f32     = 520

__device__ __forceinline__ uint32_t pack_bf2(__nv_bfloat16 lo, __nv_bfloat16 hi) {
    __nv_bfloat162 t = __halves2bfloat162(lo, hi);
    return *(uint32_t*)&t;
}

__global__ __launch_bounds__(256) void la_phase2(const float* __restrict__ Q,
                                                 float* __restrict__ O) {
    extern __shared__ char sm[];
    const int bh = blockIdx.x;
    const int rb = blockIdx.y;
    const float* Qh = Q + (size_t)bh * SEQ * DIM + (size_t)rb * 128 * DIM;
    float* Oh       = O + (size_t)bh * SEQ * DIM + (size_t)rb * 128 * DIM;

    const int tid  = threadIdx.x;
    const int lane = tid & 31;
    const int wid  = tid >> 5;

    if ((rb % 5) < 3) {
        // ===================== TENSOR engine (R5-proven) =====================
        __nv_bfloat16* As = (__nv_bfloat16*)sm;
        __nv_bfloat16* Bs = (__nv_bfloat16*)(sm + A_BYTES);

#pragma unroll
        for (int l = 0; l < 8; l++) {
            int idx = l * 256 + tid;
            int m = idx >> 4;
            int k = (idx & 15) * 4;
            float4 q = *(const float4*)(Qh + (size_t)m * DIM + k);
            q.x = fmaxf(q.x, 0.f); q.y = fmaxf(q.y, 0.f);
            q.z = fmaxf(q.z, 0.f); q.w = fmaxf(q.w, 0.f);
            __nv_bfloat16 hx = __float2bfloat16_rn(q.x), hy = __float2bfloat16_rn(q.y);
            __nv_bfloat16 hz = __float2bfloat16_rn(q.z), hw = __float2bfloat16_rn(q.w);
            __nv_bfloat16 lx = __float2bfloat16_rn(q.x - __bfloat162float(hx));
            __nv_bfloat16 ly = __float2bfloat16_rn(q.y - __bfloat162float(hy));
            __nv_bfloat16 lz = __float2bfloat16_rn(q.z - __bfloat162float(hz));
            __nv_bfloat16 lw = __float2bfloat16_rn(q.w - __bfloat162float(hw));
            __nv_bfloat16* row = As + (size_t)m * KPAD2;
            *(uint2*)(row + k)      = make_uint2(pack_bf2(hx, hy), pack_bf2(hz, hw));
            *(uint2*)(row + 64 + k) = make_uint2(pack_bf2(lx, ly), pack_bf2(lz, lw));
        }
        const float* Bg = g_kvT + (size_t)bh * 72 * DIM;
        for (int idx = tid; idx < 72 * 16; idx += 256) {
            int n = idx >> 4;
            int k = (idx & 15) * 4;
            float4 b = *(const float4*)(Bg + (size_t)n * DIM + k);
            __nv_bfloat16 hx = __float2bfloat16_rn(b.x), hy = __float2bfloat16_rn(b.y);
            __nv_bfloat16 hz = __float2bfloat16_rn(b.z), hw = __float2bfloat16_rn(b.w);
            __nv_bfloat16 lx = __float2bfloat16_rn(b.x - __bfloat162float(hx));
            __nv_bfloat16 ly = __float2bfloat16_rn(b.y - __bfloat162float(hy));
            __nv_bfloat16 lz = __float2bfloat16_rn(b.z - __bfloat162float(hz));
            __nv_bfloat16 lw = __float2bfloat16_rn(b.w - __bfloat162float(hw));
            __nv_bfloat16* row = Bs + (size_t)n * KPAD2;
            *(uint2*)(row + k)      = make_uint2(pack_bf2(hx, hy), pack_bf2(hz, hw));
            *(uint2*)(row + 64 + k) = make_uint2(pack_bf2(lx, ly), pack_bf2(lz, lw));
        }
        __syncthreads();

        const int m0 = wid * 16;
        uint32_t Abase = (uint32_t)__cvta_generic_to_shared(As);
        uint32_t Bbase = (uint32_t)__cvta_generic_to_shared(Bs);
        uint32_t aAddr = Abase + (uint32_t)(m0 + (lane & 15)) * (KPAD2 * 2)
                       + (uint32_t)(lane >> 4) * 16;
        uint32_t bAddr = Bbase + (uint32_t)(lane & 7) * (KPAD2 * 2)
                       + (uint32_t)((lane >> 3) & 1) * 16;

        constexpr int aOffs[12] = {0,32,64,96, 0,32,64,96, 128,160,192,224};
        constexpr int bOffs[12] = {0,32,64,96, 128,160,192,224, 0,32,64,96};

        float acc[9][4];
#pragma unroll
        for (int j = 0; j < 9; j++)
#pragma unroll
            for (int r = 0; r < 4; r++) acc[j][r] = 0.f;

#pragma unroll
        for (int ks = 0; ks < 12; ks++) {
            uint32_t a0, a1, a2, a3;
            asm volatile("ldmatrix.sync.aligned.m8n8.x4.shared.b16 {%0,%1,%2,%3}, [%4];"
                         : "=r"(a0), "=r"(a1), "=r"(a2), "=r"(a3)
                         : "r"(aAddr + aOffs[ks]));
#pragma unroll
            for (int j = 0; j < 9; j++) {
                uint32_t b0, b1;
                asm volatile("ldmatrix.sync.aligned.m8n8.x2.shared.b16 {%0,%1}, [%2];"
                             : "=r"(b0), "=r"(b1)
                             : "r"(bAddr + j * (8 * KPAD2 * 2) + bOffs[ks]));
                asm volatile(
                    "mma.sync.aligned.m16n8k16.row.col.f32.bf16.bf16.f32 "
                    "{%0,%1,%2,%3}, {%4,%5,%6,%7}, {%8,%9}, {%0,%1,%2,%3};"
                    : "+f"(acc[j][0]), "+f"(acc[j][1]), "+f"(acc[j][2]), "+f"(acc[j][3])
                    : "r"(a0), "r"(a1), "r"(a2), "r"(a3), "r"(b0), "r"(b1));
            }
        }

        const int g = lane >> 2;
        float nlo = __shfl_sync(0xffffffffu, acc[8][0], lane & ~3);
        float nhi = __shfl_sync(0xffffffffu, acc[8][2], lane & ~3);
        float ilo = 1.f / fmaxf(nlo, 1e-6f);
        float ihi = 1.f / fmaxf(nhi, 1e-6f);

        float* O0 = Oh + (size_t)(m0 + g) * DIM + 2 * (lane & 3);
        float* O1 = O0 + 8 * DIM;
#pragma unroll
        for (int j = 0; j < 8; j++) {
            *(float2*)(O0 + j * 8) = make_float2(acc[j][0] * ilo, acc[j][1] * ilo);
            *(float2*)(O1 + j * 8) = make_float2(acc[j][2] * ihi, acc[j][3] * ihi);
        }
    } else {
        // ===================== FMA engine (R2-proven, 128 rows) ==============
        float* kvs  = (float*)(sm + F_KV);   // [64][68] swizzled
        float* qs   = (float*)(sm + F_QS);   // [128][36] dup'd relu(Q) per pass
        float* kssd = (float*)(sm + F_KS);   // [130]

        const int tx = tid & 7;              // e col group
        const int ty = tid >> 3;             // 0..31, rows ty*4..+3
        const int kc = swz(tx * 8);

        const float4* kvg = (const float4*)(g_kv + (size_t)bh * DIM * DIM);
#pragma unroll
        for (int l = 0; l < 4; l++) {
            int idx = l * 256 + tid;
            int r  = idx >> 4;
            int c4 = idx & 15;
            *(float4*)&kvs[r * 68 + swz(c4 * 4)] = kvg[idx];
        }
        if (tid < DIM) {
            float s = g_ks[bh * DIM + tid];
            kssd[2 * tid] = s; kssd[2 * tid + 1] = s;
        }

        u64 acc[4][4];
        u64 nrm2[4];
#pragma unroll
        for (int i = 0; i < 4; i++) {
            nrm2[i] = 0ull;
#pragma unroll
            for (int j = 0; j < 4; j++) acc[i][j] = 0ull;
        }

        for (int pass = 0; pass < 4; pass++) {
            __syncthreads();
            // stage relu(Q) dup'd, cols [pass*16,+16): 512 float4 / 256 thr = 2
#pragma unroll
            for (int l = 0; l < 2; l++) {
                int idx = l * 256 + tid;
                int row = idx >> 2;
                int cg  = idx & 3;
                float4 q = *(const float4*)(Qh + (size_t)row * DIM + pass * 16 + cg * 4);
                q.x = fmaxf(q.x, 0.f); q.y = fmaxf(q.y, 0.f);
                q.z = fmaxf(q.z, 0.f); q.w = fmaxf(q.w, 0.f);
                *(float4*)&qs[row * 36 + cg * 8]     = make_float4(q.x, q.x, q.y, q.y);
                *(float4*)&qs[row * 36 + cg * 8 + 4] = make_float4(q.z, q.z, q.w, q.w);
            }
            __syncthreads();

#pragma unroll
            for (int p = 0; p < 8; p++) {
                const int d0 = pass * 16 + 2 * p;
                u64 ks0 = *(const u64*)&kssd[2 * d0];
                u64 ks1 = *(const u64*)&kssd[2 * d0 + 2];
                ulonglong2 a_lo = *(const ulonglong2*)&kvs[d0 * 68 + kc];
                ulonglong2 a_hi = *(const ulonglong2*)&kvs[d0 * 68 + kc + 4];
                ulonglong2 b_lo = *(const ulonglong2*)&kvs[(d0 + 1) * 68 + kc];
                ulonglong2 b_hi = *(const ulonglong2*)&kvs[(d0 + 1) * 68 + kc + 4];
#pragma unroll
                for (int i = 0; i < 4; i++) {
                    ulonglong2 qd = *(const ulonglong2*)&qs[(ty * 4 + i) * 36 + p * 4];
                    fma2(nrm2[i], qd.x, ks0);
                    fma2(nrm2[i], qd.y, ks1);
                    fma2(acc[i][0], qd.x, a_lo.x); fma2(acc[i][1], qd.x, a_lo.y);
                    fma2(acc[i][2], qd.x, a_hi.x); fma2(acc[i][3], qd.x, a_hi.y);
                    fma2(acc[i][0], qd.y, b_lo.x); fma2(acc[i][1], qd.y, b_lo.y);
                    fma2(acc[i][2], qd.y, b_hi.x); fma2(acc[i][3], qd.y, b_hi.y);
                }
            }
        }

#pragma unroll
        for (int i = 0; i < 4; i++) {
            float nl, nh;
            unpack2(nrm2[i], nl, nh);
            float inv = 1.f / fmaxf(nl, 1e-6f);
            float o0, o1, o2, o3, o4, o5, o6, o7;
            unpack2(acc[i][0], o0, o1);
            unpack2(acc[i][1], o2, o3);
            unpack2(acc[i][2], o4, o5);
            unpack2(acc[i][3], o6, o7);
            int row = ty * 4 + i;
            *(float4*)&Oh[(size_t)row * DIM + tx * 8] =
                make_float4(o0 * inv, o1 * inv, o2 * inv, o3 * inv);
            *(float4*)&Oh[(size_t)row * DIM + tx * 8 + 4] =
                make_float4(o4 * inv, o5 * inv, o6 * inv, o7 * inv);
        }
    }
}

// ---------------------------------------------------------------------------
extern "C" void kernel_launch(void* const* d_in, const int* in_sizes, int n_in,
                              void* d_out, int out_size) {
    const float* q = (const float*)d_in[0];
    const float* k = (const float*)d_in[1];
    const float* v = (const float*)d_in[2];
    float* o = (float*)d_out;

    static bool configured = false;
    if (!configured) {
        cudaFuncSetAttribute(la_phase2, cudaFuncAttributeMaxDynamicSharedMemorySize,
                             P2_SMEM);
        configured = true;
    }

    la_phase1<<<dim3(BH, NCHUNK), 64>>>(k, v);
    la_reduce<<<BH, 256>>>();
    la_phase2<<<dim3(BH, SEQ / 128), 256, P2_SMEM>>>(q, o);
}

// round 11
// speedup vs baseline: 1.2028x; 1.1797x over previous
#include <cuda_runtime.h>
#include <cuda_bf16.h>
#include <cstdint>

#define BH     64
#define SEQ    8192
#define DIM    64
#define NCHUNK 32
#define CHUNK  (SEQ / NCHUNK)   // 256
#define TS     16
#define NT     (CHUNK / TS)     // 16

typedef unsigned long long u64;

// Scratch (allocation-free: __device__ globals)
__device__ float g_kv_part[BH * NCHUNK * DIM * DIM];  // 32 MB
__device__ float g_ks_part[BH * NCHUNK * DIM];
__device__ float g_kvT[BH * 64 * DIM];                // kv^T: [e][d]
__device__ float g_ks [BH * DIM];                     // ksum

// ---- packed f32x2 helpers ---------------------------------------------------
__device__ __forceinline__ u64 pack2(float lo, float hi) {
    u64 r;
    asm("mov.b64 %0, {%1, %2};" : "=l"(r) : "f"(lo), "f"(hi));
    return r;
}
__device__ __forceinline__ void unpack2(u64 v, float& lo, float& hi) {
    asm("mov.b64 {%0, %1}, %2;" : "=f"(lo), "=f"(hi) : "l"(v));
}
__device__ __forceinline__ void fma2(u64& d, u64 a, u64 b) {
    asm("fma.rn.f32x2 %0, %1, %2, %0;" : "+l"(d) : "l"(a), "l"(b));
}
// ---- cp.async helpers --------------------------------------------------------
__device__ __forceinline__ void cp16(void* s, const void* g) {
    uint32_t sa = (uint32_t)__cvta_generic_to_shared(s);
    asm volatile("cp.async.cg.shared.global [%0], [%1], 16;"
                 :: "r"(sa), "l"(g) : "memory");
}
#define CP_COMMIT() asm volatile("cp.async.commit_group;" ::: "memory")
#define CP_WAIT1()  asm volatile("cp.async.wait_group 1;" ::: "memory")

// ---------------------------------------------------------------------------
// Phase 1 (unchanged, measured best): partial kv = relu(K)^T @ V, ksum.
// ---------------------------------------------------------------------------
__global__ __launch_bounds__(64) void la_phase1(const float* __restrict__ K,
                                                const float* __restrict__ V) {
    const int bh = blockIdx.x, chunk = blockIdx.y;
    const float* Kh = K + (size_t)bh * SEQ * DIM + (size_t)chunk * CHUNK * DIM;
    const float* Vh = V + (size_t)bh * SEQ * DIM + (size_t)chunk * CHUNK * DIM;

    __shared__ float Ks[2][TS][DIM];
    __shared__ float Vs[2][TS][DIM];

    const int t  = threadIdx.x;
    const int tx = t & 7;
    const int ty = t >> 3;

    int crow[4], ccol[4];
#pragma unroll
    for (int l = 0; l < 4; l++) {
        int idx = l * 64 + t;
        crow[l] = idx >> 4;
        ccol[l] = (idx & 15) * 4;
    }

    u64 acc[8][4];
    float ksum[8];
#pragma unroll
    for (int i = 0; i < 8; i++) {
        ksum[i] = 0.f;
#pragma unroll
        for (int j = 0; j < 4; j++) acc[i][j] = 0ull;
    }

#pragma unroll
    for (int p = 0; p < 2; p++) {
#pragma unroll
        for (int l = 0; l < 4; l++) {
            cp16(&Ks[p][crow[l]][ccol[l]],
                 Kh + (size_t)(p * TS + crow[l]) * DIM + ccol[l]);
            cp16(&Vs[p][crow[l]][ccol[l]],
                 Vh + (size_t)(p * TS + crow[l]) * DIM + ccol[l]);
        }
        CP_COMMIT();
    }

    for (int tl = 0; tl < NT; tl++) {
        CP_WAIT1();
        __syncthreads();
        const int b = tl & 1;

#pragma unroll 8
        for (int s = 0; s < TS; s++) {
            float4 ka = *(const float4*)&Ks[b][s][ty * 8];
            float4 kb = *(const float4*)&Ks[b][s][ty * 8 + 4];
            ulonglong2 va = *(const ulonglong2*)&Vs[b][s][tx * 8];
            ulonglong2 vb = *(const ulonglong2*)&Vs[b][s][tx * 8 + 4];
            float kf[8] = {ka.x, ka.y, ka.z, ka.w, kb.x, kb.y, kb.z, kb.w};
#pragma unroll
            for (int i = 0; i < 8; i++) {
                float km = fmaxf(kf[i], 0.f);
                ksum[i] += km;
                u64 k2 = pack2(km, km);
                fma2(acc[i][0], k2, va.x);
                fma2(acc[i][1], k2, va.y);
                fma2(acc[i][2], k2, vb.x);
                fma2(acc[i][3], k2, vb.y);
            }
        }
        __syncthreads();

        if (tl + 2 < NT) {
#pragma unroll
            for (int l = 0; l < 4; l++) {
                cp16(&Ks[b][crow[l]][ccol[l]],
                     Kh + (size_t)((tl + 2) * TS + crow[l]) * DIM + ccol[l]);
                cp16(&Vs[b][crow[l]][ccol[l]],
                     Vh + (size_t)((tl + 2) * TS + crow[l]) * DIM + ccol[l]);
            }
        }
        CP_COMMIT();
    }

    float* kvp = g_kv_part + ((size_t)bh * NCHUNK + chunk) * DIM * DIM;
#pragma unroll
    for (int i = 0; i < 8; i++) {
        int d = ty * 8 + i;
        float o0, o1, o2, o3, o4, o5, o6, o7;
        unpack2(acc[i][0], o0, o1);
        unpack2(acc[i][1], o2, o3);
        unpack2(acc[i][2], o4, o5);
        unpack2(acc[i][3], o6, o7);
        *(float4*)&kvp[d * DIM + tx * 8]     = make_float4(o0, o1, o2, o3);
        *(float4*)&kvp[d * DIM + tx * 8 + 4] = make_float4(o4, o5, o6, o7);
    }
    if (tx == 0) {
#pragma unroll
        for (int i = 0; i < 8; i++)
            g_ks_part[((size_t)bh * NCHUNK + chunk) * DIM + ty * 8 + i] = ksum[i];
    }
}

// ---------------------------------------------------------------------------
// Reduce partials -> g_kvT[bh][64][64] (kv^T) and g_ks[bh][64]
// ---------------------------------------------------------------------------
__global__ __launch_bounds__(256) void la_reduce() {
    const int bh  = blockIdx.x;
    const int tid = threadIdx.x;
    float* outT = g_kvT + (size_t)bh * 64 * DIM;
    for (int idx = tid; idx < DIM * DIM; idx += 256) {
        int d = idx >> 6, e = idx & 63;
        float sum = 0.f;
#pragma unroll
        for (int c = 0; c < NCHUNK; c++)
            sum += g_kv_part[((size_t)bh * NCHUNK + c) * DIM * DIM + idx];
        outT[e * DIM + d] = sum;
    }
    if (tid < DIM) {
        float s = 0.f;
#pragma unroll
        for (int c = 0; c < NCHUNK; c++)
            s += g_ks_part[((size_t)bh * NCHUNK + c) * DIM + tid];
        g_ks[bh * DIM + tid] = s;
    }
}

// ===========================================================================
// Phase 2: mma.sync bf16, 3-term split, dedup smem [hi(64)|lo(64)].
// 8 n-tiles only (no padding / normalizer column). Normalizer computed on the
// fma pipe per warp: lane half-rows dot relu(Q) (gmem) with g_ks, shfl-reduce.
// ===========================================================================
#define KPAD2 136
#define A_BYTES (128 * KPAD2 * 2)   // 34816
#define B_BYTES (64 * KPAD2 * 2)    // 17408
#define P2_SMEM (A_BYTES + B_BYTES) // 52224

__device__ __forceinline__ uint32_t pack_bf2(__nv_bfloat16 lo, __nv_bfloat16 hi) {
    __nv_bfloat162 t = __halves2bfloat162(lo, hi);
    return *(uint32_t*)&t;
}

__global__ __launch_bounds__(256) void la_phase2(const float* __restrict__ Q,
                                                 float* __restrict__ O) {
    extern __shared__ char sm[];
    __nv_bfloat16* As = (__nv_bfloat16*)sm;
    __nv_bfloat16* Bs = (__nv_bfloat16*)(sm + A_BYTES);

    const int bh = blockIdx.x;
    const int rb = blockIdx.y;
    const float* Qh = Q + (size_t)bh * SEQ * DIM + (size_t)rb * 128 * DIM;

    const int tid  = threadIdx.x;
    const int lane = tid & 31;
    const int wid  = tid >> 5;
    const int m0   = wid * 16;

    // ---- normalizer (fma pipe; overlaps with staging/MMA stalls) ----
    // lane pairs: row = m0 + (lane>>1), half = lane&1 covers d-range half*32..+31
    float nacc;
    {
        const int nrow = lane >> 1, nhalf = lane & 1;
        const float* qrow = Qh + (size_t)(m0 + nrow) * DIM + nhalf * 32;
        const float* ksp  = g_ks + bh * DIM + nhalf * 32;
        nacc = 0.f;
#pragma unroll
        for (int c = 0; c < 8; c++) {
            float4 qv = *(const float4*)(qrow + c * 4);
            float4 kv = *(const float4*)(ksp + c * 4);
            nacc += fmaxf(qv.x, 0.f) * kv.x + fmaxf(qv.y, 0.f) * kv.y
                  + fmaxf(qv.z, 0.f) * kv.z + fmaxf(qv.w, 0.f) * kv.w;
        }
        nacc += __shfl_xor_sync(0xffffffffu, nacc, 1);
    }

    // ---- stage A = relu(Q) [hi|lo]: 2048 float4 / 256 thr = 8 each ----
#pragma unroll
    for (int l = 0; l < 8; l++) {
        int idx = l * 256 + tid;
        int m = idx >> 4;
        int k = (idx & 15) * 4;
        float4 q = *(const float4*)(Qh + (size_t)m * DIM + k);
        q.x = fmaxf(q.x, 0.f); q.y = fmaxf(q.y, 0.f);
        q.z = fmaxf(q.z, 0.f); q.w = fmaxf(q.w, 0.f);
        __nv_bfloat16 hx = __float2bfloat16_rn(q.x), hy = __float2bfloat16_rn(q.y);
        __nv_bfloat16 hz = __float2bfloat16_rn(q.z), hw = __float2bfloat16_rn(q.w);
        __nv_bfloat16 lx = __float2bfloat16_rn(q.x - __bfloat162float(hx));
        __nv_bfloat16 ly = __float2bfloat16_rn(q.y - __bfloat162float(hy));
        __nv_bfloat16 lz = __float2bfloat16_rn(q.z - __bfloat162float(hz));
        __nv_bfloat16 lw = __float2bfloat16_rn(q.w - __bfloat162float(hw));
        __nv_bfloat16* row = As + (size_t)m * KPAD2;
        *(uint2*)(row + k)      = make_uint2(pack_bf2(hx, hy), pack_bf2(hz, hw));
        *(uint2*)(row + 64 + k) = make_uint2(pack_bf2(lx, ly), pack_bf2(lz, lw));
    }
    // ---- stage B = g_kvT (64 rows) [hi|lo]: 1024 float4 / 256 thr = 4 each ----
    const float* Bg = g_kvT + (size_t)bh * 64 * DIM;
#pragma unroll
    for (int l = 0; l < 4; l++) {
        int idx = l * 256 + tid;
        int n = idx >> 4;
        int k = (idx & 15) * 4;
        float4 b = *(const float4*)(Bg + (size_t)n * DIM + k);
        __nv_bfloat16 hx = __float2bfloat16_rn(b.x), hy = __float2bfloat16_rn(b.y);
        __nv_bfloat16 hz = __float2bfloat16_rn(b.z), hw = __float2bfloat16_rn(b.w);
        __nv_bfloat16 lx = __float2bfloat16_rn(b.x - __bfloat162float(hx));
        __nv_bfloat16 ly = __float2bfloat16_rn(b.y - __bfloat162float(hy));
        __nv_bfloat16 lz = __float2bfloat16_rn(b.z - __bfloat162float(hz));
        __nv_bfloat16 lw = __float2bfloat16_rn(b.w - __bfloat162float(hw));
        __nv_bfloat16* row = Bs + (size_t)n * KPAD2;
        *(uint2*)(row + k)      = make_uint2(pack_bf2(hx, hy), pack_bf2(hz, hw));
        *(uint2*)(row + 64 + k) = make_uint2(pack_bf2(lx, ly), pack_bf2(lz, lw));
    }
    __syncthreads();

    // ---- mainloop: 12 k-steps x 8 n-tiles ----
    uint32_t Abase = (uint32_t)__cvta_generic_to_shared(As);
    uint32_t Bbase = (uint32_t)__cvta_generic_to_shared(Bs);
    uint32_t aAddr = Abase + (uint32_t)(m0 + (lane & 15)) * (KPAD2 * 2)
                   + (uint32_t)(lane >> 4) * 16;
    uint32_t bAddr = Bbase + (uint32_t)(lane & 7) * (KPAD2 * 2)
                   + (uint32_t)((lane >> 3) & 1) * 16;

    constexpr int aOffs[12] = {0,32,64,96, 0,32,64,96, 128,160,192,224};
    constexpr int bOffs[12] = {0,32,64,96, 128,160,192,224, 0,32,64,96};

    float acc[8][4];
#pragma unroll
    for (int j = 0; j < 8; j++)
#pragma unroll
        for (int r = 0; r < 4; r++) acc[j][r] = 0.f;

#pragma unroll
    for (int ks = 0; ks < 12; ks++) {
        uint32_t a0, a1, a2, a3;
        asm volatile("ldmatrix.sync.aligned.m8n8.x4.shared.b16 {%0,%1,%2,%3}, [%4];"
                     : "=r"(a0), "=r"(a1), "=r"(a2), "=r"(a3)
                     : "r"(aAddr + aOffs[ks]));
#pragma unroll
        for (int j = 0; j < 8; j++) {
            uint32_t b0, b1;
            asm volatile("ldmatrix.sync.aligned.m8n8.x2.shared.b16 {%0,%1}, [%2];"
                         : "=r"(b0), "=r"(b1)
                         : "r"(bAddr + j * (8 * KPAD2 * 2) + bOffs[ks]));
            asm volatile(
                "mma.sync.aligned.m16n8k16.row.col.f32.bf16.bf16.f32 "
                "{%0,%1,%2,%3}, {%4,%5,%6,%7}, {%8,%9}, {%0,%1,%2,%3};"
                : "+f"(acc[j][0]), "+f"(acc[j][1]), "+f"(acc[j][2]), "+f"(acc[j][3])
                : "r"(a0), "r"(a1), "r"(a2), "r"(a3), "r"(b0), "r"(b1));
        }
    }

    // ---- epilogue: fetch normalizers from the lanes that computed them ----
    const int g = lane >> 2;
    float n0 = __shfl_sync(0xffffffffu, nacc, (g << 1));        // row m0 + g
    float n1 = __shfl_sync(0xffffffffu, nacc, (g << 1) + 16);   // row m0 + g + 8
    float ilo = 1.f / fmaxf(n0, 1e-6f);
    float ihi = 1.f / fmaxf(n1, 1e-6f);

    float* O0 = O + ((size_t)bh * SEQ + (size_t)rb * 128 + m0 + g) * DIM + 2 * (lane & 3);
    float* O1 = O0 + 8 * DIM;
#pragma unroll
    for (int j = 0; j < 8; j++) {
        *(float2*)(O0 + j * 8) = make_float2(acc[j][0] * ilo, acc[j][1] * ilo);
        *(float2*)(O1 + j * 8) = make_float2(acc[j][2] * ihi, acc[j][3] * ihi);
    }
}

// ---------------------------------------------------------------------------
extern "C" void kernel_launch(void* const* d_in, const int* in_sizes, int n_in,
                              void* d_out, int out_size) {
    const float* q = (const float*)d_in[0];
    const float* k = (const float*)d_in[1];
    const float* v = (const float*)d_in[2];
    float* o = (float*)d_out;

    static bool configured = false;
    if (!configured) {
        cudaFuncSetAttribute(la_phase2, cudaFuncAttributeMaxDynamicSharedMemorySize,
                             P2_SMEM);
        configured = true;
    }

    la_phase1<<<dim3(BH, NCHUNK), 64>>>(k, v);
    la_reduce<<<BH, 256>>>();
    la_phase2<<<dim3(BH, SEQ / 128), 256, P2_SMEM>>>(q, o);
}

// round 12
// speedup vs baseline: 1.5769x; 1.3110x over previous
#include <cuda_runtime.h>
#include <cuda_fp16.h>
#include <cstdint>

#define BH     64
#define SEQ    8192
#define DIM    64
#define NCHUNK 32
#define CHUNK  (SEQ / NCHUNK)   // 256
#define TS     16
#define NT     (CHUNK / TS)     // 16

typedef unsigned long long u64;

// Scratch (allocation-free: __device__ globals)
__device__ float g_kv_part[BH * NCHUNK * DIM * DIM];  // 32 MB
__device__ float g_ks_part[BH * NCHUNK * DIM];
__device__ float g_kvT[BH * 72 * DIM];                // [e(64)+ksum(1)+pad(7)][d(64)]

// ---- packed f32x2 helpers ---------------------------------------------------
__device__ __forceinline__ u64 pack2(float lo, float hi) {
    u64 r;
    asm("mov.b64 %0, {%1, %2};" : "=l"(r) : "f"(lo), "f"(hi));
    return r;
}
__device__ __forceinline__ void unpack2(u64 v, float& lo, float& hi) {
    asm("mov.b64 {%0, %1}, %2;" : "=f"(lo), "=f"(hi) : "l"(v));
}
__device__ __forceinline__ void fma2(u64& d, u64 a, u64 b) {
    asm("fma.rn.f32x2 %0, %1, %2, %0;" : "+l"(d) : "l"(a), "l"(b));
}
// ---- cp.async helpers --------------------------------------------------------
__device__ __forceinline__ void cp16(void* s, const void* g) {
    uint32_t sa = (uint32_t)__cvta_generic_to_shared(s);
    asm volatile("cp.async.cg.shared.global [%0], [%1], 16;"
                 :: "r"(sa), "l"(g) : "memory");
}
#define CP_COMMIT() asm volatile("cp.async.commit_group;" ::: "memory")
#define CP_WAIT1()  asm volatile("cp.async.wait_group 1;" ::: "memory")

// ---------------------------------------------------------------------------
// Phase 1 (unchanged, measured best): partial kv = relu(K)^T @ V, ksum.
// ---------------------------------------------------------------------------
__global__ __launch_bounds__(64) void la_phase1(const float* __restrict__ K,
                                                const float* __restrict__ V) {
    const int bh = blockIdx.x, chunk = blockIdx.y;
    const float* Kh = K + (size_t)bh * SEQ * DIM + (size_t)chunk * CHUNK * DIM;
    const float* Vh = V + (size_t)bh * SEQ * DIM + (size_t)chunk * CHUNK * DIM;

    __shared__ float Ks[2][TS][DIM];
    __shared__ float Vs[2][TS][DIM];

    const int t  = threadIdx.x;
    const int tx = t & 7;
    const int ty = t >> 3;

    int crow[4], ccol[4];
#pragma unroll
    for (int l = 0; l < 4; l++) {
        int idx = l * 64 + t;
        crow[l] = idx >> 4;
        ccol[l] = (idx & 15) * 4;
    }

    u64 acc[8][4];
    float ksum[8];
#pragma unroll
    for (int i = 0; i < 8; i++) {
        ksum[i] = 0.f;
#pragma unroll
        for (int j = 0; j < 4; j++) acc[i][j] = 0ull;
    }

#pragma unroll
    for (int p = 0; p < 2; p++) {
#pragma unroll
        for (int l = 0; l < 4; l++) {
            cp16(&Ks[p][crow[l]][ccol[l]],
                 Kh + (size_t)(p * TS + crow[l]) * DIM + ccol[l]);
            cp16(&Vs[p][crow[l]][ccol[l]],
                 Vh + (size_t)(p * TS + crow[l]) * DIM + ccol[l]);
        }
        CP_COMMIT();
    }

    for (int tl = 0; tl < NT; tl++) {
        CP_WAIT1();
        __syncthreads();
        const int b = tl & 1;

#pragma unroll 8
        for (int s = 0; s < TS; s++) {
            float4 ka = *(const float4*)&Ks[b][s][ty * 8];
            float4 kb = *(const float4*)&Ks[b][s][ty * 8 + 4];
            ulonglong2 va = *(const ulonglong2*)&Vs[b][s][tx * 8];
            ulonglong2 vb = *(const ulonglong2*)&Vs[b][s][tx * 8 + 4];
            float kf[8] = {ka.x, ka.y, ka.z, ka.w, kb.x, kb.y, kb.z, kb.w};
#pragma unroll
            for (int i = 0; i < 8; i++) {
                float km = fmaxf(kf[i], 0.f);
                ksum[i] += km;
                u64 k2 = pack2(km, km);
                fma2(acc[i][0], k2, va.x);
                fma2(acc[i][1], k2, va.y);
                fma2(acc[i][2], k2, vb.x);
                fma2(acc[i][3], k2, vb.y);
            }
        }
        __syncthreads();

        if (tl + 2 < NT) {
#pragma unroll
            for (int l = 0; l < 4; l++) {
                cp16(&Ks[b][crow[l]][ccol[l]],
                     Kh + (size_t)((tl + 2) * TS + crow[l]) * DIM + ccol[l]);
                cp16(&Vs[b][crow[l]][ccol[l]],
                     Vh + (size_t)((tl + 2) * TS + crow[l]) * DIM + ccol[l]);
            }
        }
        CP_COMMIT();
    }

    float* kvp = g_kv_part + ((size_t)bh * NCHUNK + chunk) * DIM * DIM;
#pragma unroll
    for (int i = 0; i < 8; i++) {
        int d = ty * 8 + i;
        float o0, o1, o2, o3, o4, o5, o6, o7;
        unpack2(acc[i][0], o0, o1);
        unpack2(acc[i][1], o2, o3);
        unpack2(acc[i][2], o4, o5);
        unpack2(acc[i][3], o6, o7);
        *(float4*)&kvp[d * DIM + tx * 8]     = make_float4(o0, o1, o2, o3);
        *(float4*)&kvp[d * DIM + tx * 8 + 4] = make_float4(o4, o5, o6, o7);
    }
    if (tx == 0) {
#pragma unroll
        for (int i = 0; i < 8; i++)
            g_ks_part[((size_t)bh * NCHUNK + chunk) * DIM + ty * 8 + i] = ksum[i];
    }
}

// ---------------------------------------------------------------------------
// Reduce partials -> g_kvT[bh][72][64] (kv^T, ksum row 64, zero pad 65-71)
// ---------------------------------------------------------------------------
__global__ __launch_bounds__(256) void la_reduce() {
    const int bh  = blockIdx.x;
    const int tid = threadIdx.x;
    float* outT = g_kvT + (size_t)bh * 72 * DIM;
    for (int idx = tid; idx < DIM * DIM; idx += 256) {
        int d = idx >> 6, e = idx & 63;
        float sum = 0.f;
#pragma unroll
        for (int c = 0; c < NCHUNK; c++)
            sum += g_kv_part[((size_t)bh * NCHUNK + c) * DIM * DIM + idx];
        outT[e * DIM + d] = sum;
    }
    if (tid < DIM) {
        float s = 0.f;
#pragma unroll
        for (int c = 0; c < NCHUNK; c++)
            s += g_ks_part[((size_t)bh * NCHUNK + c) * DIM + tid];
        outT[64 * DIM + tid] = s;
    }
    for (int i = tid; i < 7 * DIM; i += 256)
        outT[65 * DIM + i] = 0.f;
}

// ===========================================================================
// Phase 2: mma.sync FP16 2-TERM split (exact fp16 products in fp32 accum):
//   out = A_hi @ B_hi + A_hi @ B_lo  (= A_hi @ B; dropped A_lo·B ~ 2^-11)
// A smem = hi only (rows of 64 fp16, stride 72). B smem = [hi(64)|lo(64)],
// stride 136. 8 k-steps x 9 n-tiles (col 64 = normalizer, as R5-proven).
// ===========================================================================
#define KPADA 72                     // A row stride in fp16 (144 B, odd 16B mult)
#define KPADB 136                    // B row stride in fp16 (272 B, odd 16B mult)
#define A_BYTES (128 * KPADA * 2)    // 18432
#define B_BYTES (72 * KPADB * 2)     // 19584
#define P2_SMEM (A_BYTES + B_BYTES)  // 38016

__device__ __forceinline__ uint32_t pack_h2(__half a, __half b) {
    __half2 t = __halves2half2(a, b);
    return *(uint32_t*)&t;
}

__global__ __launch_bounds__(256) void la_phase2(const float* __restrict__ Q,
                                                 float* __restrict__ O) {
    extern __shared__ char sm[];
    __half* As = (__half*)sm;
    __half* Bs = (__half*)(sm + A_BYTES);

    const int bh = blockIdx.x;
    const int rb = blockIdx.y;
    const float* Qh = Q + (size_t)bh * SEQ * DIM + (size_t)rb * 128 * DIM;

    const int tid  = threadIdx.x;
    const int lane = tid & 31;
    const int wid  = tid >> 5;

    // ---- stage A = fp16(relu(Q)) hi only: 2048 float4 / 256 thr = 8 each ----
#pragma unroll
    for (int l = 0; l < 8; l++) {
        int idx = l * 256 + tid;
        int m = idx >> 4;
        int k = (idx & 15) * 4;
        float4 q = *(const float4*)(Qh + (size_t)m * DIM + k);
        q.x = fmaxf(q.x, 0.f); q.y = fmaxf(q.y, 0.f);
        q.z = fmaxf(q.z, 0.f); q.w = fmaxf(q.w, 0.f);
        *(uint2*)(As + (size_t)m * KPADA + k) =
            make_uint2(pack_h2(__float2half_rn(q.x), __float2half_rn(q.y)),
                       pack_h2(__float2half_rn(q.z), __float2half_rn(q.w)));
    }
    // ---- stage B = g_kvT [hi|lo]: 1152 float4 / 256 thr ----
    const float* Bg = g_kvT + (size_t)bh * 72 * DIM;
    for (int idx = tid; idx < 72 * 16; idx += 256) {
        int n = idx >> 4;
        int k = (idx & 15) * 4;
        float4 b = *(const float4*)(Bg + (size_t)n * DIM + k);
        __half hx = __float2half_rn(b.x), hy = __float2half_rn(b.y);
        __half hz = __float2half_rn(b.z), hw = __float2half_rn(b.w);
        __half lx = __float2half_rn(b.x - __half2float(hx));
        __half ly = __float2half_rn(b.y - __half2float(hy));
        __half lz = __float2half_rn(b.z - __half2float(hz));
        __half lw = __float2half_rn(b.w - __half2float(hw));
        __half* row = Bs + (size_t)n * KPADB;
        *(uint2*)(row + k)      = make_uint2(pack_h2(hx, hy), pack_h2(hz, hw));
        *(uint2*)(row + 64 + k) = make_uint2(pack_h2(lx, ly), pack_h2(lz, lw));
    }
    __syncthreads();

    // ---- mainloop: 8 k-steps x 9 n-tiles ----
    const int m0 = wid * 16;
    uint32_t Abase = (uint32_t)__cvta_generic_to_shared(As);
    uint32_t Bbase = (uint32_t)__cvta_generic_to_shared(Bs);
    uint32_t aAddr = Abase + (uint32_t)(m0 + (lane & 15)) * (KPADA * 2)
                   + (uint32_t)(lane >> 4) * 16;
    uint32_t bAddr = Bbase + (uint32_t)(lane & 7) * (KPADB * 2)
                   + (uint32_t)((lane >> 3) & 1) * 16;

    // term 1 (ks 0-3): A_hi x B_hi ; term 2 (ks 4-7): A_hi x B_lo
    constexpr int aOffs[8] = {0,32,64,96, 0,32,64,96};
    constexpr int bOffs[8] = {0,32,64,96, 128,160,192,224};

    float acc[9][4];
#pragma unroll
    for (int j = 0; j < 9; j++)
#pragma unroll
        for (int r = 0; r < 4; r++) acc[j][r] = 0.f;

#pragma unroll
    for (int ks = 0; ks < 8; ks++) {
        uint32_t a0, a1, a2, a3;
        asm volatile("ldmatrix.sync.aligned.m8n8.x4.shared.b16 {%0,%1,%2,%3}, [%4];"
                     : "=r"(a0), "=r"(a1), "=r"(a2), "=r"(a3)
                     : "r"(aAddr + aOffs[ks]));
#pragma unroll
        for (int j = 0; j < 9; j++) {
            uint32_t b0, b1;
            asm volatile("ldmatrix.sync.aligned.m8n8.x2.shared.b16 {%0,%1}, [%2];"
                         : "=r"(b0), "=r"(b1)
                         : "r"(bAddr + j * (8 * KPADB * 2) + bOffs[ks]));
            asm volatile(
                "mma.sync.aligned.m16n8k16.row.col.f32.f16.f16.f32 "
                "{%0,%1,%2,%3}, {%4,%5,%6,%7}, {%8,%9}, {%0,%1,%2,%3};"
                : "+f"(acc[j][0]), "+f"(acc[j][1]), "+f"(acc[j][2]), "+f"(acc[j][3])
                : "r"(a0), "r"(a1), "r"(a2), "r"(a3), "r"(b0), "r"(b1));
        }
    }

    // ---- epilogue: normalizer = col 64 (n-tile 8, local col 0) ----
    const int g = lane >> 2;
    float nlo = __shfl_sync(0xffffffffu, acc[8][0], lane & ~3);
    float nhi = __shfl_sync(0xffffffffu, acc[8][2], lane & ~3);
    float ilo = 1.f / fmaxf(nlo, 1e-6f);
    float ihi = 1.f / fmaxf(nhi, 1e-6f);

    float* O0 = O + ((size_t)bh * SEQ + (size_t)rb * 128 + m0 + g) * DIM + 2 * (lane & 3);
    float* O1 = O0 + 8 * DIM;
#pragma unroll
    for (int j = 0; j < 8; j++) {
        *(float2*)(O0 + j * 8) = make_float2(acc[j][0] * ilo, acc[j][1] * ilo);
        *(float2*)(O1 + j * 8) = make_float2(acc[j][2] * ihi, acc[j][3] * ihi);
    }
}

// ---------------------------------------------------------------------------
extern "C" void kernel_launch(void* const* d_in, const int* in_sizes, int n_in,
                              void* d_out, int out_size) {
    const float* q = (const float*)d_in[0];
    const float* k = (const float*)d_in[1];
    const float* v = (const float*)d_in[2];
    float* o = (float*)d_out;

    static bool configured = false;
    if (!configured) {
        cudaFuncSetAttribute(la_phase2, cudaFuncAttributeMaxDynamicSharedMemorySize,
                             P2_SMEM);
        configured = true;
    }

    la_phase1<<<dim3(BH, NCHUNK), 64>>>(k, v);
    la_reduce<<<BH, 256>>>();
    la_phase2<<<dim3(BH, SEQ / 128), 256, P2_SMEM>>>(q, o);
}

// round 13
// speedup vs baseline: 1.8295x; 1.1602x over previous
#include <cuda_runtime.h>
#include <cuda_fp16.h>
#include <cstdint>

#define BH     64
#define SEQ    8192
#define DIM    64
#define NCHUNK 32
#define CHUNK  (SEQ / NCHUNK)   // 256
#define P1TS   128              // s rows per staged tile (2 tiles per chunk)

typedef unsigned long long u64;

// Scratch (allocation-free: __device__ globals)
__device__ float g_kv_part[BH * NCHUNK * DIM * DIM];  // 32 MB
__device__ float g_ks_part[BH * NCHUNK * DIM];
__device__ float g_kvT[BH * 72 * DIM];                // [e(64)+ksum(1)+pad(7)][d(64)]

__device__ __forceinline__ uint32_t pack_h2(__half a, __half b) {
    __half2 t = __halves2half2(a, b);
    return *(uint32_t*)&t;
}

// ===========================================================================
// Phase 1 on mma.sync FP16, 2-term split + ones-column ksum:
//   D[d(64) x 72] = relu(K)_hi^T @ [V_hi | ones] + relu(K)_hi^T @ [V_lo | 0]
// K smem [s][d] fp16 stride 72 el (144B, rows 4 banks apart).
// V smem [s][ Vh(0-63) | ones+pad(64-71) | Vl(72-135) | zeros(136-143) ]
//   stride 152 el (304B, rows 12 banks apart). Both read via ldmatrix.trans.
// 128 threads (4 warps), warp w owns d rows w*16..+15; 9 n-tiles.
// ===========================================================================
#define KSTR 72                       // K smem stride (fp16 elements)
#define VSTR 152                      // V smem stride (fp16 elements)
#define P1_K_BYTES (P1TS * KSTR * 2)  // 18432
#define P1_V_BYTES (P1TS * VSTR * 2)  // 38912
#define P1_SMEM (P1_K_BYTES + P1_V_BYTES) // 57344

__global__ __launch_bounds__(128) void la_phase1(const float* __restrict__ K,
                                                 const float* __restrict__ V) {
    extern __shared__ char sm1[];
    __half* Ks = (__half*)sm1;
    __half* Vs = (__half*)(sm1 + P1_K_BYTES);

    const int bh = blockIdx.x, chunk = blockIdx.y;
    const float* Kh = K + (size_t)bh * SEQ * DIM + (size_t)chunk * CHUNK * DIM;
    const float* Vh = V + (size_t)bh * SEQ * DIM + (size_t)chunk * CHUNK * DIM;

    const int tid  = threadIdx.x;
    const int lane = tid & 31;
    const int wid  = tid >> 5;
    const int m0   = wid * 16;        // d rows for this warp

    // ldmatrix.trans addressing (element offsets computed per tile below):
    // A x4: lane -> storage row k = (lane&7) + 8*(lane>>4), col = m0 + 8*((lane>>3)&1)
    const int aRow = (lane & 7) + ((lane >> 4) << 3);
    const int aCol = m0 + (((lane >> 3) & 1) << 3);
    // B x2: lane -> storage row k = (lane&7) + 8*((lane>>3)&1), col = n0
    const int bRow = (lane & 7) + (((lane >> 3) & 1) << 3);

    uint32_t Kbase = (uint32_t)__cvta_generic_to_shared(Ks);
    uint32_t Vbase = (uint32_t)__cvta_generic_to_shared(Vs);
    uint32_t aAddr0 = Kbase + (uint32_t)(aRow * KSTR + aCol) * 2;
    uint32_t bAddr0 = Vbase + (uint32_t)(bRow * VSTR) * 2;

    float acc[9][4];
#pragma unroll
    for (int j = 0; j < 9; j++)
#pragma unroll
        for (int r = 0; r < 4; r++) acc[j][r] = 0.f;

    for (int tile = 0; tile < CHUNK / P1TS; tile++) {
        const float* Kt = Kh + (size_t)tile * P1TS * DIM;
        const float* Vt = Vh + (size_t)tile * P1TS * DIM;
        __syncthreads();
        // ---- stage K (relu, fp16 hi) and V (hi/lo): 2048 float4 each / 128 thr
#pragma unroll
        for (int l = 0; l < 16; l++) {
            int idx = l * 128 + tid;
            int s = idx >> 4;
            int c = (idx & 15) * 4;
            float4 kq = *(const float4*)(Kt + (size_t)s * DIM + c);
            kq.x = fmaxf(kq.x, 0.f); kq.y = fmaxf(kq.y, 0.f);
            kq.z = fmaxf(kq.z, 0.f); kq.w = fmaxf(kq.w, 0.f);
            *(uint2*)(Ks + (size_t)s * KSTR + c) =
                make_uint2(pack_h2(__float2half_rn(kq.x), __float2half_rn(kq.y)),
                           pack_h2(__float2half_rn(kq.z), __float2half_rn(kq.w)));
            float4 vq = *(const float4*)(Vt + (size_t)s * DIM + c);
            __half hx = __float2half_rn(vq.x), hy = __float2half_rn(vq.y);
            __half hz = __float2half_rn(vq.z), hw = __float2half_rn(vq.w);
            __half lx = __float2half_rn(vq.x - __half2float(hx));
            __half ly = __float2half_rn(vq.y - __half2float(hy));
            __half lz = __float2half_rn(vq.z - __half2float(hz));
            __half lw = __float2half_rn(vq.w - __half2float(hw));
            __half* vrow = Vs + (size_t)s * VSTR;
            *(uint2*)(vrow + c)      = make_uint2(pack_h2(hx, hy), pack_h2(hz, hw));
            *(uint2*)(vrow + 72 + c) = make_uint2(pack_h2(lx, ly), pack_h2(lz, lw));
        }
        // const columns: [64..71] = {1,0,...}, [136..143] = {0,...}  (1 row/thread)
        {
            __half* vrow = Vs + (size_t)tid * VSTR;
            *(uint4*)(vrow + 64)  = make_uint4(0x3C00u, 0u, 0u, 0u);
            *(uint4*)(vrow + 136) = make_uint4(0u, 0u, 0u, 0u);
        }
        __syncthreads();

        // ---- MMA: 8 k-steps x (2 terms x 9 n-tiles) ----
#pragma unroll
        for (int ks = 0; ks < 8; ks++) {
            uint32_t a0, a1, a2, a3;
            asm volatile("ldmatrix.sync.aligned.m8n8.x4.trans.shared.b16 "
                         "{%0,%1,%2,%3}, [%4];"
                         : "=r"(a0), "=r"(a1), "=r"(a2), "=r"(a3)
                         : "r"(aAddr0 + (uint32_t)(ks * 16 * KSTR * 2)));
#pragma unroll
            for (int t = 0; t < 2; t++) {
#pragma unroll
                for (int j = 0; j < 9; j++) {
                    uint32_t b0, b1;
                    asm volatile("ldmatrix.sync.aligned.m8n8.x2.trans.shared.b16 "
                                 "{%0,%1}, [%2];"
                                 : "=r"(b0), "=r"(b1)
                                 : "r"(bAddr0 + (uint32_t)(ks * 16 * VSTR * 2
                                       + (t * 72 + j * 8) * 2)));
                    asm volatile(
                        "mma.sync.aligned.m16n8k16.row.col.f32.f16.f16.f32 "
                        "{%0,%1,%2,%3}, {%4,%5,%6,%7}, {%8,%9}, {%0,%1,%2,%3};"
                        : "+f"(acc[j][0]), "+f"(acc[j][1]),
                          "+f"(acc[j][2]), "+f"(acc[j][3])
                        : "r"(a0), "r"(a1), "r"(a2), "r"(a3), "r"(b0), "r"(b1));
                }
            }
        }
    }

    // ---- epilogue: D rows = d, cols 0-63 -> kv_part; col 64 -> ksum ----
    const int g = lane >> 2;          // row-in-half
    const int c2 = (lane & 3) * 2;    // col pair base
    float* kvp = g_kv_part + ((size_t)bh * NCHUNK + chunk) * DIM * DIM;
#pragma unroll
    for (int j = 0; j < 8; j++) {
        *(float2*)(kvp + (size_t)(m0 + g) * DIM + j * 8 + c2) =
            make_float2(acc[j][0], acc[j][1]);
        *(float2*)(kvp + (size_t)(m0 + g + 8) * DIM + j * 8 + c2) =
            make_float2(acc[j][2], acc[j][3]);
    }
    if ((lane & 3) == 0) {
        float* ksp = g_ks_part + ((size_t)bh * NCHUNK + chunk) * DIM;
        ksp[m0 + g]     = acc[8][0];
        ksp[m0 + g + 8] = acc[8][2];
    }
}

// ---------------------------------------------------------------------------
// Reduce partials -> g_kvT[bh][72][64] (kv^T, ksum row 64, zero pad 65-71)
// ---------------------------------------------------------------------------
__global__ __launch_bounds__(256) void la_reduce() {
    const int bh  = blockIdx.x;
    const int tid = threadIdx.x;
    float* outT = g_kvT + (size_t)bh * 72 * DIM;
    for (int idx = tid; idx < DIM * DIM; idx += 256) {
        int d = idx >> 6, e = idx & 63;
        float sum = 0.f;
#pragma unroll
        for (int c = 0; c < NCHUNK; c++)
            sum += g_kv_part[((size_t)bh * NCHUNK + c) * DIM * DIM + idx];
        outT[e * DIM + d] = sum;
    }
    if (tid < DIM) {
        float s = 0.f;
#pragma unroll
        for (int c = 0; c < NCHUNK; c++)
            s += g_ks_part[((size_t)bh * NCHUNK + c) * DIM + tid];
        outT[64 * DIM + tid] = s;
    }
    for (int i = tid; i < 7 * DIM; i += 256)
        outT[65 * DIM + i] = 0.f;
}

// ===========================================================================
// Phase 2 (R12-proven): mma.sync FP16 2-term split.
//   out = A_hi @ B_hi + A_hi @ B_lo ; col 64 = normalizer.
// ===========================================================================
#define KPADA 72
#define KPADB 136
#define A_BYTES (128 * KPADA * 2)    // 18432
#define B_BYTES (72 * KPADB * 2)     // 19584
#define P2_SMEM (A_BYTES + B_BYTES)  // 38016

__global__ __launch_bounds__(256) void la_phase2(const float* __restrict__ Q,
                                                 float* __restrict__ O) {
    extern __shared__ char sm[];
    __half* As = (__half*)sm;
    __half* Bs = (__half*)(sm + A_BYTES);

    const int bh = blockIdx.x;
    const int rb = blockIdx.y;
    const float* Qh = Q + (size_t)bh * SEQ * DIM + (size_t)rb * 128 * DIM;

    const int tid  = threadIdx.x;
    const int lane = tid & 31;
    const int wid  = tid >> 5;

    // ---- stage A = fp16(relu(Q)) hi only ----
#pragma unroll
    for (int l = 0; l < 8; l++) {
        int idx = l * 256 + tid;
        int m = idx >> 4;
        int k = (idx & 15) * 4;
        float4 q = *(const float4*)(Qh + (size_t)m * DIM + k);
        q.x = fmaxf(q.x, 0.f); q.y = fmaxf(q.y, 0.f);
        q.z = fmaxf(q.z, 0.f); q.w = fmaxf(q.w, 0.f);
        *(uint2*)(As + (size_t)m * KPADA + k) =
            make_uint2(pack_h2(__float2half_rn(q.x), __float2half_rn(q.y)),
                       pack_h2(__float2half_rn(q.z), __float2half_rn(q.w)));
    }
    // ---- stage B = g_kvT [hi|lo] ----
    const float* Bg = g_kvT + (size_t)bh * 72 * DIM;
    for (int idx = tid; idx < 72 * 16; idx += 256) {
        int n = idx >> 4;
        int k = (idx & 15) * 4;
        float4 b = *(const float4*)(Bg + (size_t)n * DIM + k);
        __half hx = __float2half_rn(b.x), hy = __float2half_rn(b.y);
        __half hz = __float2half_rn(b.z), hw = __float2half_rn(b.w);
        __half lx = __float2half_rn(b.x - __half2float(hx));
        __half ly = __float2half_rn(b.y - __half2float(hy));
        __half lz = __float2half_rn(b.z - __half2float(hz));
        __half lw = __float2half_rn(b.w - __half2float(hw));
        __half* row = Bs + (size_t)n * KPADB;
        *(uint2*)(row + k)      = make_uint2(pack_h2(hx, hy), pack_h2(hz, hw));
        *(uint2*)(row + 64 + k) = make_uint2(pack_h2(lx, ly), pack_h2(lz, lw));
    }
    __syncthreads();

    // ---- mainloop: 8 k-steps x 9 n-tiles ----
    const int m0 = wid * 16;
    uint32_t Abase = (uint32_t)__cvta_generic_to_shared(As);
    uint32_t Bbase = (uint32_t)__cvta_generic_to_shared(Bs);
    uint32_t aAddr = Abase + (uint32_t)(m0 + (lane & 15)) * (KPADA * 2)
                   + (uint32_t)(lane >> 4) * 16;
    uint32_t bAddr = Bbase + (uint32_t)(lane & 7) * (KPADB * 2)
                   + (uint32_t)((lane >> 3) & 1) * 16;

    constexpr int aOffs[8] = {0,32,64,96, 0,32,64,96};
    constexpr int bOffs[8] = {0,32,64,96, 128,160,192,224};

    float acc[9][4];
#pragma unroll
    for (int j = 0; j < 9; j++)
#pragma unroll
        for (int r = 0; r < 4; r++) acc[j][r] = 0.f;

#pragma unroll
    for (int ks = 0; ks < 8; ks++) {
        uint32_t a0, a1, a2, a3;
        asm volatile("ldmatrix.sync.aligned.m8n8.x4.shared.b16 {%0,%1,%2,%3}, [%4];"
                     : "=r"(a0), "=r"(a1), "=r"(a2), "=r"(a3)
                     : "r"(aAddr + aOffs[ks]));
#pragma unroll
        for (int j = 0; j < 9; j++) {
            uint32_t b0, b1;
            asm volatile("ldmatrix.sync.aligned.m8n8.x2.shared.b16 {%0,%1}, [%2];"
                         : "=r"(b0), "=r"(b1)
                         : "r"(bAddr + j * (8 * KPADB * 2) + bOffs[ks]));
            asm volatile(
                "mma.sync.aligned.m16n8k16.row.col.f32.f16.f16.f32 "
                "{%0,%1,%2,%3}, {%4,%5,%6,%7}, {%8,%9}, {%0,%1,%2,%3};"
                : "+f"(acc[j][0]), "+f"(acc[j][1]), "+f"(acc[j][2]), "+f"(acc[j][3])
                : "r"(a0), "r"(a1), "r"(a2), "r"(a3), "r"(b0), "r"(b1));
        }
    }

    // ---- epilogue ----
    const int g = lane >> 2;
    float nlo = __shfl_sync(0xffffffffu, acc[8][0], lane & ~3);
    float nhi = __shfl_sync(0xffffffffu, acc[8][2], lane & ~3);
    float ilo = 1.f / fmaxf(nlo, 1e-6f);
    float ihi = 1.f / fmaxf(nhi, 1e-6f);

    float* O0 = O + ((size_t)bh * SEQ + (size_t)rb * 128 + m0 + g) * DIM + 2 * (lane & 3);
    float* O1 = O0 + 8 * DIM;
#pragma unroll
    for (int j = 0; j < 8; j++) {
        *(float2*)(O0 + j * 8) = make_float2(acc[j][0] * ilo, acc[j][1] * ilo);
        *(float2*)(O1 + j * 8) = make_float2(acc[j][2] * ihi, acc[j][3] * ihi);
    }
}

// ---------------------------------------------------------------------------
extern "C" void kernel_launch(void* const* d_in, const int* in_sizes, int n_in,
                              void* d_out, int out_size) {
    const float* q = (const float*)d_in[0];
    const float* k = (const float*)d_in[1];
    const float* v = (const float*)d_in[2];
    float* o = (float*)d_out;

    static bool configured = false;
    if (!configured) {
        cudaFuncSetAttribute(la_phase1, cudaFuncAttributeMaxDynamicSharedMemorySize,
                             P1_SMEM);
        cudaFuncSetAttribute(la_phase2, cudaFuncAttributeMaxDynamicSharedMemorySize,
                             P2_SMEM);
        configured = true;
    }

    la_phase1<<<dim3(BH, NCHUNK), 128, P1_SMEM>>>(k, v);
    la_reduce<<<BH, 256>>>();
    la_phase2<<<dim3(BH, SEQ / 128), 256, P2_SMEM>>>(q, o);
}

// round 14
// speedup vs baseline: 2.0040x; 1.0954x over previous
#include <cuda_runtime.h>
#include <cuda_fp16.h>
#include <cstdint>

#define BH     64
#define SEQ    8192
#define DIM    64
#define NCHUNK 32
#define CHUNK  (SEQ / NCHUNK)   // 256
#define P1TS   128              // s rows per staged tile (2 tiles per chunk)

typedef unsigned long long u64;

// Scratch (allocation-free: __device__ globals)
__device__ float g_kv_part[BH * NCHUNK * DIM * DIM];  // 32 MB
__device__ float g_ks_part[BH * NCHUNK * DIM];
__device__ float g_kvT[BH * 72 * DIM];                // [e(64)+ksum(1)+pad(7)][d(64)]

__device__ __forceinline__ uint32_t pack_h2(__half a, __half b) {
    __half2 t = __halves2half2(a, b);
    return *(uint32_t*)&t;
}

// ===========================================================================
// Phase 1, pure fp16 HMMA + ones-column ksum:
//   D[d(64) x 72] = fp16(relu(K))^T @ [fp16(V) | ones]
// K smem [s][d] stride 72 el (144B; 36w = 4 mod 32 -> conflict-free trans).
// V smem [s][ V(0-63) | ones+pad(64-71) ] stride 88 el (176B; 44w = 12 mod 32).
// 128 threads (4 warps), warp w owns d rows w*16..+15; 9 n-tiles, 8 k-steps/tile.
// ===========================================================================
#define KSTR 72
#define VSTR 88
#define P1_K_BYTES (P1TS * KSTR * 2)      // 18432
#define P1_V_BYTES (P1TS * VSTR * 2)      // 22528
#define P1_SMEM (P1_K_BYTES + P1_V_BYTES) // 40960

__global__ __launch_bounds__(128) void la_phase1(const float* __restrict__ K,
                                                 const float* __restrict__ V) {
    extern __shared__ char sm1[];
    __half* Ks = (__half*)sm1;
    __half* Vs = (__half*)(sm1 + P1_K_BYTES);

    const int bh = blockIdx.x, chunk = blockIdx.y;
    const float* Kh = K + (size_t)bh * SEQ * DIM + (size_t)chunk * CHUNK * DIM;
    const float* Vh = V + (size_t)bh * SEQ * DIM + (size_t)chunk * CHUNK * DIM;

    const int tid  = threadIdx.x;
    const int lane = tid & 31;
    const int wid  = tid >> 5;
    const int m0   = wid * 16;        // d rows for this warp

    // ldmatrix.trans lane->address maps
    const int aRow = (lane & 7) + ((lane >> 4) << 3);
    const int aCol = m0 + (((lane >> 3) & 1) << 3);
    const int bRow = (lane & 7) + (((lane >> 3) & 1) << 3);

    uint32_t Kbase = (uint32_t)__cvta_generic_to_shared(Ks);
    uint32_t Vbase = (uint32_t)__cvta_generic_to_shared(Vs);
    uint32_t aAddr0 = Kbase + (uint32_t)(aRow * KSTR + aCol) * 2;
    uint32_t bAddr0 = Vbase + (uint32_t)(bRow * VSTR) * 2;

    float acc[9][4];
#pragma unroll
    for (int j = 0; j < 9; j++)
#pragma unroll
        for (int r = 0; r < 4; r++) acc[j][r] = 0.f;

    for (int tile = 0; tile < CHUNK / P1TS; tile++) {
        const float* Kt = Kh + (size_t)tile * P1TS * DIM;
        const float* Vt = Vh + (size_t)tile * P1TS * DIM;
        __syncthreads();
        // ---- stage K (relu, fp16) and V (fp16): 2048 float4 each / 128 thr
#pragma unroll
        for (int l = 0; l < 16; l++) {
            int idx = l * 128 + tid;
            int s = idx >> 4;
            int c = (idx & 15) * 4;
            float4 kq = *(const float4*)(Kt + (size_t)s * DIM + c);
            kq.x = fmaxf(kq.x, 0.f); kq.y = fmaxf(kq.y, 0.f);
            kq.z = fmaxf(kq.z, 0.f); kq.w = fmaxf(kq.w, 0.f);
            *(uint2*)(Ks + (size_t)s * KSTR + c) =
                make_uint2(pack_h2(__float2half_rn(kq.x), __float2half_rn(kq.y)),
                           pack_h2(__float2half_rn(kq.z), __float2half_rn(kq.w)));
            float4 vq = *(const float4*)(Vt + (size_t)s * DIM + c);
            *(uint2*)(Vs + (size_t)s * VSTR + c) =
                make_uint2(pack_h2(__float2half_rn(vq.x), __float2half_rn(vq.y)),
                           pack_h2(__float2half_rn(vq.z), __float2half_rn(vq.w)));
        }
        // ones column block: cols [64..71] = {1,0,0,0,0,0,0,0} per row
        {
            __half* vrow = Vs + (size_t)tid * VSTR;
            *(uint4*)(vrow + 64) = make_uint4(0x3C00u, 0u, 0u, 0u);
        }
        __syncthreads();

        // ---- MMA: 8 k-steps x 9 n-tiles ----
#pragma unroll
        for (int ks = 0; ks < 8; ks++) {
            uint32_t a0, a1, a2, a3;
            asm volatile("ldmatrix.sync.aligned.m8n8.x4.trans.shared.b16 "
                         "{%0,%1,%2,%3}, [%4];"
                         : "=r"(a0), "=r"(a1), "=r"(a2), "=r"(a3)
                         : "r"(aAddr0 + (uint32_t)(ks * 16 * KSTR * 2)));
#pragma unroll
            for (int j = 0; j < 9; j++) {
                uint32_t b0, b1;
                asm volatile("ldmatrix.sync.aligned.m8n8.x2.trans.shared.b16 "
                             "{%0,%1}, [%2];"
                             : "=r"(b0), "=r"(b1)
                             : "r"(bAddr0 + (uint32_t)(ks * 16 * VSTR * 2 + j * 16)));
                asm volatile(
                    "mma.sync.aligned.m16n8k16.row.col.f32.f16.f16.f32 "
                    "{%0,%1,%2,%3}, {%4,%5,%6,%7}, {%8,%9}, {%0,%1,%2,%3};"
                    : "+f"(acc[j][0]), "+f"(acc[j][1]),
                      "+f"(acc[j][2]), "+f"(acc[j][3])
                    : "r"(a0), "r"(a1), "r"(a2), "r"(a3), "r"(b0), "r"(b1));
            }
        }
    }

    // ---- epilogue: cols 0-63 -> kv_part; col 64 -> ksum ----
    const int g = lane >> 2;
    const int c2 = (lane & 3) * 2;
    float* kvp = g_kv_part + ((size_t)bh * NCHUNK + chunk) * DIM * DIM;
#pragma unroll
    for (int j = 0; j < 8; j++) {
        *(float2*)(kvp + (size_t)(m0 + g) * DIM + j * 8 + c2) =
            make_float2(acc[j][0], acc[j][1]);
        *(float2*)(kvp + (size_t)(m0 + g + 8) * DIM + j * 8 + c2) =
            make_float2(acc[j][2], acc[j][3]);
    }
    if ((lane & 3) == 0) {
        float* ksp = g_ks_part + ((size_t)bh * NCHUNK + chunk) * DIM;
        ksp[m0 + g]     = acc[8][0];
        ksp[m0 + g + 8] = acc[8][2];
    }
}

// ---------------------------------------------------------------------------
// Reduce partials -> g_kvT[bh][72][64] (kv^T, ksum row 64, zero pad 65-71)
// ---------------------------------------------------------------------------
__global__ __launch_bounds__(256) void la_reduce() {
    const int bh  = blockIdx.x;
    const int tid = threadIdx.x;
    float* outT = g_kvT + (size_t)bh * 72 * DIM;
    for (int idx = tid; idx < DIM * DIM; idx += 256) {
        int d = idx >> 6, e = idx & 63;
        float sum = 0.f;
#pragma unroll
        for (int c = 0; c < NCHUNK; c++)
            sum += g_kv_part[((size_t)bh * NCHUNK + c) * DIM * DIM + idx];
        outT[e * DIM + d] = sum;
    }
    if (tid < DIM) {
        float s = 0.f;
#pragma unroll
        for (int c = 0; c < NCHUNK; c++)
            s += g_ks_part[((size_t)bh * NCHUNK + c) * DIM + tid];
        outT[64 * DIM + tid] = s;
    }
    for (int i = tid; i < 7 * DIM; i += 256)
        outT[65 * DIM + i] = 0.f;
}

// ===========================================================================
// Phase 2, pure fp16 HMMA: out = fp16(relu(Q)) @ fp16([kv^T ; ksum])^T.
// 4 k-steps x 9 n-tiles (col 64 = normalizer). 256 threads.
// ===========================================================================
#define KPADA 72
#define KPADB 72
#define A_BYTES (128 * KPADA * 2)    // 18432
#define B_BYTES (72 * KPADB * 2)     // 10368
#define P2_SMEM (A_BYTES + B_BYTES)  // 28800

__global__ __launch_bounds__(256) void la_phase2(const float* __restrict__ Q,
                                                 float* __restrict__ O) {
    extern __shared__ char sm[];
    __half* As = (__half*)sm;
    __half* Bs = (__half*)(sm + A_BYTES);

    const int bh = blockIdx.x;
    const int rb = blockIdx.y;
    const float* Qh = Q + (size_t)bh * SEQ * DIM + (size_t)rb * 128 * DIM;

    const int tid  = threadIdx.x;
    const int lane = tid & 31;
    const int wid  = tid >> 5;

    // ---- stage A = fp16(relu(Q)): 2048 float4 / 256 thr = 8 each ----
#pragma unroll
    for (int l = 0; l < 8; l++) {
        int idx = l * 256 + tid;
        int m = idx >> 4;
        int k = (idx & 15) * 4;
        float4 q = *(const float4*)(Qh + (size_t)m * DIM + k);
        q.x = fmaxf(q.x, 0.f); q.y = fmaxf(q.y, 0.f);
        q.z = fmaxf(q.z, 0.f); q.w = fmaxf(q.w, 0.f);
        *(uint2*)(As + (size_t)m * KPADA + k) =
            make_uint2(pack_h2(__float2half_rn(q.x), __float2half_rn(q.y)),
                       pack_h2(__float2half_rn(q.z), __float2half_rn(q.w)));
    }
    // ---- stage B = fp16(g_kvT): 1152 float4 / 256 thr ----
    const float* Bg = g_kvT + (size_t)bh * 72 * DIM;
    for (int idx = tid; idx < 72 * 16; idx += 256) {
        int n = idx >> 4;
        int k = (idx & 15) * 4;
        float4 b = *(const float4*)(Bg + (size_t)n * DIM + k);
        *(uint2*)(Bs + (size_t)n * KPADB + k) =
            make_uint2(pack_h2(__float2half_rn(b.x), __float2half_rn(b.y)),
                       pack_h2(__float2half_rn(b.z), __float2half_rn(b.w)));
    }
    __syncthreads();

    // ---- mainloop: 4 k-steps x 9 n-tiles ----
    const int m0 = wid * 16;
    uint32_t Abase = (uint32_t)__cvta_generic_to_shared(As);
    uint32_t Bbase = (uint32_t)__cvta_generic_to_shared(Bs);
    uint32_t aAddr = Abase + (uint32_t)(m0 + (lane & 15)) * (KPADA * 2)
                   + (uint32_t)(lane >> 4) * 16;
    uint32_t bAddr = Bbase + (uint32_t)(lane & 7) * (KPADB * 2)
                   + (uint32_t)((lane >> 3) & 1) * 16;

    float acc[9][4];
#pragma unroll
    for (int j = 0; j < 9; j++)
#pragma unroll
        for (int r = 0; r < 4; r++) acc[j][r] = 0.f;

#pragma unroll
    for (int ks = 0; ks < 4; ks++) {
        uint32_t a0, a1, a2, a3;
        asm volatile("ldmatrix.sync.aligned.m8n8.x4.shared.b16 {%0,%1,%2,%3}, [%4];"
                     : "=r"(a0), "=r"(a1), "=r"(a2), "=r"(a3)
                     : "r"(aAddr + ks * 32));
#pragma unroll
        for (int j = 0; j < 9; j++) {
            uint32_t b0, b1;
            asm volatile("ldmatrix.sync.aligned.m8n8.x2.shared.b16 {%0,%1}, [%2];"
                         : "=r"(b0), "=r"(b1)
                         : "r"(bAddr + j * (8 * KPADB * 2) + ks * 32));
            asm volatile(
                "mma.sync.aligned.m16n8k16.row.col.f32.f16.f16.f32 "
                "{%0,%1,%2,%3}, {%4,%5,%6,%7}, {%8,%9}, {%0,%1,%2,%3};"
                : "+f"(acc[j][0]), "+f"(acc[j][1]), "+f"(acc[j][2]), "+f"(acc[j][3])
                : "r"(a0), "r"(a1), "r"(a2), "r"(a3), "r"(b0), "r"(b1));
        }
    }

    // ---- epilogue ----
    const int g = lane >> 2;
    float nlo = __shfl_sync(0xffffffffu, acc[8][0], lane & ~3);
    float nhi = __shfl_sync(0xffffffffu, acc[8][2], lane & ~3);
    float ilo = 1.f / fmaxf(nlo, 1e-6f);
    float ihi = 1.f / fmaxf(nhi, 1e-6f);

    float* O0 = O + ((size_t)bh * SEQ + (size_t)rb * 128 + m0 + g) * DIM + 2 * (lane & 3);
    float* O1 = O0 + 8 * DIM;
#pragma unroll
    for (int j = 0; j < 8; j++) {
        *(float2*)(O0 + j * 8) = make_float2(acc[j][0] * ilo, acc[j][1] * ilo);
        *(float2*)(O1 + j * 8) = make_float2(acc[j][2] * ihi, acc[j][3] * ihi);
    }
}

// ---------------------------------------------------------------------------
extern "C" void kernel_launch(void* const* d_in, const int* in_sizes, int n_in,
                              void* d_out, int out_size) {
    const float* q = (const float*)d_in[0];
    const float* k = (const float*)d_in[1];
    const float* v = (const float*)d_in[2];
    float* o = (float*)d_out;

    static bool configured = false;
    if (!configured) {
        cudaFuncSetAttribute(la_phase1, cudaFuncAttributeMaxDynamicSharedMemorySize,
                             P1_SMEM);
        cudaFuncSetAttribute(la_phase2, cudaFuncAttributeMaxDynamicSharedMemorySize,
                             P2_SMEM);
        configured = true;
    }

    la_phase1<<<dim3(BH, NCHUNK), 128, P1_SMEM>>>(k, v);
    la_reduce<<<BH, 256>>>();
    la_phase2<<<dim3(BH, SEQ / 128), 256, P2_SMEM>>>(q, o);
}

// round 15
// speedup vs baseline: 2.2848x; 1.1401x over previous
#include <cuda_runtime.h>
#include <cuda_fp16.h>
#include <cstdint>

#define BH     64
#define SEQ    8192
#define DIM    64
#define NCHUNK 16
#define CHUNK  (SEQ / NCHUNK)   // 512
#define P1TS   64               // s rows per staged tile (8 tiles per chunk)

typedef unsigned long long u64;

// Scratch (allocation-free: __device__ globals)
__device__ float g_kv_part[BH * NCHUNK * DIM * DIM];  // 16 MB
__device__ float g_ks_part[BH * NCHUNK * DIM];
__device__ float g_kvT[BH * 72 * DIM];                // [e(64)+ksum(1)+pad(7)][d(64)]

__device__ __forceinline__ uint32_t pack_h2(__half a, __half b) {
    __half2 t = __halves2half2(a, b);
    return *(uint32_t*)&t;
}

// ===========================================================================
// Phase 1, pure fp16 HMMA + ones-column ksum:
//   D[d(64) x 72] = fp16(relu(K))^T @ [fp16(V) | ones]
// P1TS=64 tiles -> smem 20.5 KB -> ~10 CTAs/SM for latency hiding.
// K smem [s][d] stride 72 el; V smem [s][V|ones] stride 88 el (trans-safe).
// ===========================================================================
#define KSTR 72
#define VSTR 88
#define P1_K_BYTES (P1TS * KSTR * 2)      // 9216
#define P1_V_BYTES (P1TS * VSTR * 2)      // 11264
#define P1_SMEM (P1_K_BYTES + P1_V_BYTES) // 20480

__global__ __launch_bounds__(128) void la_phase1(const float* __restrict__ K,
                                                 const float* __restrict__ V) {
    extern __shared__ char sm1[];
    __half* Ks = (__half*)sm1;
    __half* Vs = (__half*)(sm1 + P1_K_BYTES);

    const int bh = blockIdx.x, chunk = blockIdx.y;
    const float* Kh = K + (size_t)bh * SEQ * DIM + (size_t)chunk * CHUNK * DIM;
    const float* Vh = V + (size_t)bh * SEQ * DIM + (size_t)chunk * CHUNK * DIM;

    const int tid  = threadIdx.x;
    const int lane = tid & 31;
    const int wid  = tid >> 5;
    const int m0   = wid * 16;        // d rows for this warp

    const int aRow = (lane & 7) + ((lane >> 4) << 3);
    const int aCol = m0 + (((lane >> 3) & 1) << 3);
    const int bRow = (lane & 7) + (((lane >> 3) & 1) << 3);

    uint32_t Kbase = (uint32_t)__cvta_generic_to_shared(Ks);
    uint32_t Vbase = (uint32_t)__cvta_generic_to_shared(Vs);
    uint32_t aAddr0 = Kbase + (uint32_t)(aRow * KSTR + aCol) * 2;
    uint32_t bAddr0 = Vbase + (uint32_t)(bRow * VSTR) * 2;

    float acc[9][4];
#pragma unroll
    for (int j = 0; j < 9; j++)
#pragma unroll
        for (int r = 0; r < 4; r++) acc[j][r] = 0.f;

    for (int tile = 0; tile < CHUNK / P1TS; tile++) {
        const float* Kt = Kh + (size_t)tile * P1TS * DIM;
        const float* Vt = Vh + (size_t)tile * P1TS * DIM;
        __syncthreads();
        // ---- stage K (relu, fp16) and V (fp16): 1024 float4 each / 128 thr
#pragma unroll
        for (int l = 0; l < 8; l++) {
            int idx = l * 128 + tid;
            int s = idx >> 4;
            int c = (idx & 15) * 4;
            float4 kq = *(const float4*)(Kt + (size_t)s * DIM + c);
            kq.x = fmaxf(kq.x, 0.f); kq.y = fmaxf(kq.y, 0.f);
            kq.z = fmaxf(kq.z, 0.f); kq.w = fmaxf(kq.w, 0.f);
            *(uint2*)(Ks + (size_t)s * KSTR + c) =
                make_uint2(pack_h2(__float2half_rn(kq.x), __float2half_rn(kq.y)),
                           pack_h2(__float2half_rn(kq.z), __float2half_rn(kq.w)));
            float4 vq = *(const float4*)(Vt + (size_t)s * DIM + c);
            *(uint2*)(Vs + (size_t)s * VSTR + c) =
                make_uint2(pack_h2(__float2half_rn(vq.x), __float2half_rn(vq.y)),
                           pack_h2(__float2half_rn(vq.z), __float2half_rn(vq.w)));
        }
        // ones column block: cols [64..71] = {1,0,0,0,0,0,0,0} per row
        if (tid < P1TS) {
            __half* vrow = Vs + (size_t)tid * VSTR;
            *(uint4*)(vrow + 64) = make_uint4(0x3C00u, 0u, 0u, 0u);
        }
        __syncthreads();

        // ---- MMA: 4 k-steps x 9 n-tiles ----
#pragma unroll
        for (int ks = 0; ks < 4; ks++) {
            uint32_t a0, a1, a2, a3;
            asm volatile("ldmatrix.sync.aligned.m8n8.x4.trans.shared.b16 "
                         "{%0,%1,%2,%3}, [%4];"
                         : "=r"(a0), "=r"(a1), "=r"(a2), "=r"(a3)
                         : "r"(aAddr0 + (uint32_t)(ks * 16 * KSTR * 2)));
#pragma unroll
            for (int j = 0; j < 9; j++) {
                uint32_t b0, b1;
                asm volatile("ldmatrix.sync.aligned.m8n8.x2.trans.shared.b16 "
                             "{%0,%1}, [%2];"
                             : "=r"(b0), "=r"(b1)
                             : "r"(bAddr0 + (uint32_t)(ks * 16 * VSTR * 2 + j * 16)));
                asm volatile(
                    "mma.sync.aligned.m16n8k16.row.col.f32.f16.f16.f32 "
                    "{%0,%1,%2,%3}, {%4,%5,%6,%7}, {%8,%9}, {%0,%1,%2,%3};"
                    : "+f"(acc[j][0]), "+f"(acc[j][1]),
                      "+f"(acc[j][2]), "+f"(acc[j][3])
                    : "r"(a0), "r"(a1), "r"(a2), "r"(a3), "r"(b0), "r"(b1));
            }
        }
    }

    // ---- epilogue: cols 0-63 -> kv_part; col 64 -> ksum ----
    const int g = lane >> 2;
    const int c2 = (lane & 3) * 2;
    float* kvp = g_kv_part + ((size_t)bh * NCHUNK + chunk) * DIM * DIM;
#pragma unroll
    for (int j = 0; j < 8; j++) {
        *(float2*)(kvp + (size_t)(m0 + g) * DIM + j * 8 + c2) =
            make_float2(acc[j][0], acc[j][1]);
        *(float2*)(kvp + (size_t)(m0 + g + 8) * DIM + j * 8 + c2) =
            make_float2(acc[j][2], acc[j][3]);
    }
    if ((lane & 3) == 0) {
        float* ksp = g_ks_part + ((size_t)bh * NCHUNK + chunk) * DIM;
        ksp[m0 + g]     = acc[8][0];
        ksp[m0 + g + 8] = acc[8][2];
    }
}

// ---------------------------------------------------------------------------
// Reduce partials -> g_kvT[bh][72][64] (kv^T, ksum row 64, zero pad 65-71)
// ---------------------------------------------------------------------------
__global__ __launch_bounds__(256) void la_reduce() {
    const int bh  = blockIdx.x;
    const int tid = threadIdx.x;
    float* outT = g_kvT + (size_t)bh * 72 * DIM;
    for (int idx = tid; idx < DIM * DIM; idx += 256) {
        int d = idx >> 6, e = idx & 63;
        float sum = 0.f;
#pragma unroll
        for (int c = 0; c < NCHUNK; c++)
            sum += g_kv_part[((size_t)bh * NCHUNK + c) * DIM * DIM + idx];
        outT[e * DIM + d] = sum;
    }
    if (tid < DIM) {
        float s = 0.f;
#pragma unroll
        for (int c = 0; c < NCHUNK; c++)
            s += g_ks_part[((size_t)bh * NCHUNK + c) * DIM + tid];
        outT[64 * DIM + tid] = s;
    }
    for (int i = tid; i < 7 * DIM; i += 256)
        outT[65 * DIM + i] = 0.f;
}

// ===========================================================================
// Phase 2, pure fp16 HMMA with REGISTER-DIRECT A fragments:
// each warp owns rows m0..m0+15; threads LDG their mma A-fragment elements
// straight from Q (documented m16n8k16 layout), relu+cvt in regs. smem = B
// only (10.4 KB). 4 k-steps x 9 n-tiles (col 64 = normalizer).
// ===========================================================================
#define KPADB 72
#define P2_SMEM (72 * KPADB * 2)    // 10368

__global__ __launch_bounds__(256) void la_phase2(const float* __restrict__ Q,
                                                 float* __restrict__ O) {
    extern __shared__ char sm[];
    __half* Bs = (__half*)sm;

    const int bh = blockIdx.x;
    const int rb = blockIdx.y;
    const float* Qh = Q + (size_t)bh * SEQ * DIM + (size_t)rb * 128 * DIM;

    const int tid  = threadIdx.x;
    const int lane = tid & 31;
    const int wid  = tid >> 5;
    const int m0   = wid * 16;
    const int g    = lane >> 2;
    const int c    = lane & 3;

    // ---- A fragments direct from gmem (16 float2 per thread, high MLP) ----
    const float* Qr0 = Qh + (size_t)(m0 + g) * DIM;
    const float* Qr8 = Qh + (size_t)(m0 + g + 8) * DIM;
    float2 x0[4], x2[4], y0[4], y2[4];
#pragma unroll
    for (int ks = 0; ks < 4; ks++) {
        x0[ks] = *(const float2*)(Qr0 + ks * 16 + 2 * c);
        x2[ks] = *(const float2*)(Qr0 + ks * 16 + 8 + 2 * c);
        y0[ks] = *(const float2*)(Qr8 + ks * 16 + 2 * c);
        y2[ks] = *(const float2*)(Qr8 + ks * 16 + 8 + 2 * c);
    }

    // ---- stage B = fp16(g_kvT): 1152 float4 / 256 thr ----
    const float* Bg = g_kvT + (size_t)bh * 72 * DIM;
    for (int idx = tid; idx < 72 * 16; idx += 256) {
        int n = idx >> 4;
        int k = (idx & 15) * 4;
        float4 b = *(const float4*)(Bg + (size_t)n * DIM + k);
        *(uint2*)(Bs + (size_t)n * KPADB + k) =
            make_uint2(pack_h2(__float2half_rn(b.x), __float2half_rn(b.y)),
                       pack_h2(__float2half_rn(b.z), __float2half_rn(b.w)));
    }

    // convert A fragments while B staging is in flight
    uint32_t af[4][4];
#pragma unroll
    for (int ks = 0; ks < 4; ks++) {
        af[ks][0] = pack_h2(__float2half_rn(fmaxf(x0[ks].x, 0.f)),
                            __float2half_rn(fmaxf(x0[ks].y, 0.f)));
        af[ks][1] = pack_h2(__float2half_rn(fmaxf(y0[ks].x, 0.f)),
                            __float2half_rn(fmaxf(y0[ks].y, 0.f)));
        af[ks][2] = pack_h2(__float2half_rn(fmaxf(x2[ks].x, 0.f)),
                            __float2half_rn(fmaxf(x2[ks].y, 0.f)));
        af[ks][3] = pack_h2(__float2half_rn(fmaxf(y2[ks].x, 0.f)),
                            __float2half_rn(fmaxf(y2[ks].y, 0.f)));
    }
    __syncthreads();

    // ---- mainloop: 4 k-steps x 9 n-tiles ----
    uint32_t Bbase = (uint32_t)__cvta_generic_to_shared(Bs);
    uint32_t bAddr = Bbase + (uint32_t)(lane & 7) * (KPADB * 2)
                   + (uint32_t)((lane >> 3) & 1) * 16;

    float acc[9][4];
#pragma unroll
    for (int j = 0; j < 9; j++)
#pragma unroll
        for (int r = 0; r < 4; r++) acc[j][r] = 0.f;

#pragma unroll
    for (int ks = 0; ks < 4; ks++) {
#pragma unroll
        for (int j = 0; j < 9; j++) {
            uint32_t b0, b1;
            asm volatile("ldmatrix.sync.aligned.m8n8.x2.shared.b16 {%0,%1}, [%2];"
                         : "=r"(b0), "=r"(b1)
                         : "r"(bAddr + j * (8 * KPADB * 2) + ks * 32));
            asm volatile(
                "mma.sync.aligned.m16n8k16.row.col.f32.f16.f16.f32 "
                "{%0,%1,%2,%3}, {%4,%5,%6,%7}, {%8,%9}, {%0,%1,%2,%3};"
                : "+f"(acc[j][0]), "+f"(acc[j][1]), "+f"(acc[j][2]), "+f"(acc[j][3])
                : "r"(af[ks][0]), "r"(af[ks][1]), "r"(af[ks][2]), "r"(af[ks][3]),
                  "r"(b0), "r"(b1));
        }
    }

    // ---- epilogue ----
    float nlo = __shfl_sync(0xffffffffu, acc[8][0], lane & ~3);
    float nhi = __shfl_sync(0xffffffffu, acc[8][2], lane & ~3);
    float ilo = 1.f / fmaxf(nlo, 1e-6f);
    float ihi = 1.f / fmaxf(nhi, 1e-6f);

    float* O0 = O + ((size_t)bh * SEQ + (size_t)rb * 128 + m0 + g) * DIM + 2 * c;
    float* O1 = O0 + 8 * DIM;
#pragma unroll
    for (int j = 0; j < 8; j++) {
        *(float2*)(O0 + j * 8) = make_float2(acc[j][0] * ilo, acc[j][1] * ilo);
        *(float2*)(O1 + j * 8) = make_float2(acc[j][2] * ihi, acc[j][3] * ihi);
    }
}

// ---------------------------------------------------------------------------
extern "C" void kernel_launch(void* const* d_in, const int* in_sizes, int n_in,
                              void* d_out, int out_size) {
    const float* q = (const float*)d_in[0];
    const float* k = (const float*)d_in[1];
    const float* v = (const float*)d_in[2];
    float* o = (float*)d_out;

    static bool configured = false;
    if (!configured) {
        cudaFuncSetAttribute(la_phase1, cudaFuncAttributeMaxDynamicSharedMemorySize,
                             P1_SMEM);
        cudaFuncSetAttribute(la_phase2, cudaFuncAttributeMaxDynamicSharedMemorySize,
                             P2_SMEM);
        configured = true;
    }

    la_phase1<<<dim3(BH, NCHUNK), 128, P1_SMEM>>>(k, v);
    la_reduce<<<BH, 256>>>();
    la_phase2<<<dim3(BH, SEQ / 128), 256, P2_SMEM>>>(q, o);
}

// round 16
// speedup vs baseline: 2.3335x; 1.0213x over previous
#include <cuda_runtime.h>
#include <cuda_fp16.h>
#include <cstdint>

#define BH     64
#define SEQ    8192
#define DIM    64
#define NCHUNK 16
#define CHUNK  (SEQ / NCHUNK)   // 512
#define P1TS   64               // s rows per staged tile (8 tiles per chunk)

typedef unsigned long long u64;

// Scratch (allocation-free: __device__ globals)
__device__ float g_kv_part[BH * NCHUNK * DIM * DIM];  // 16 MB
__device__ float g_ks_part[BH * NCHUNK * DIM];
__device__ float g_kvT[BH * 72 * DIM];                // [e(64)+ksum(1)+pad(7)][d(64)]

__device__ __forceinline__ uint32_t pack_h2(__half a, __half b) {
    __half2 t = __halves2half2(a, b);
    return *(uint32_t*)&t;
}

// ===========================================================================
// Phase 1, pure fp16 HMMA + ones-column ksum:
//   D[d(64) x 72] = fp16(relu(K))^T @ [fp16(V) | ones]
// __launch_bounds__(128,5): cap regs ~102 -> 5 CTAs/SM (was reg-limited to 4).
// ===========================================================================
#define KSTR 72
#define VSTR 88
#define P1_K_BYTES (P1TS * KSTR * 2)      // 9216
#define P1_V_BYTES (P1TS * VSTR * 2)      // 11264
#define P1_SMEM (P1_K_BYTES + P1_V_BYTES) // 20480

__global__ __launch_bounds__(128, 5) void la_phase1(const float* __restrict__ K,
                                                    const float* __restrict__ V) {
    extern __shared__ char sm1[];
    __half* Ks = (__half*)sm1;
    __half* Vs = (__half*)(sm1 + P1_K_BYTES);

    const int bh = blockIdx.x, chunk = blockIdx.y;
    const float* Kh = K + (size_t)bh * SEQ * DIM + (size_t)chunk * CHUNK * DIM;
    const float* Vh = V + (size_t)bh * SEQ * DIM + (size_t)chunk * CHUNK * DIM;

    const int tid  = threadIdx.x;
    const int lane = tid & 31;
    const int wid  = tid >> 5;
    const int m0   = wid * 16;        // d rows for this warp

    const int aRow = (lane & 7) + ((lane >> 4) << 3);
    const int aCol = m0 + (((lane >> 3) & 1) << 3);
    const int bRow = (lane & 7) + (((lane >> 3) & 1) << 3);

    uint32_t Kbase = (uint32_t)__cvta_generic_to_shared(Ks);
    uint32_t Vbase = (uint32_t)__cvta_generic_to_shared(Vs);
    uint32_t aAddr0 = Kbase + (uint32_t)(aRow * KSTR + aCol) * 2;
    uint32_t bAddr0 = Vbase + (uint32_t)(bRow * VSTR) * 2;

    float acc[9][4];
#pragma unroll
    for (int j = 0; j < 9; j++)
#pragma unroll
        for (int r = 0; r < 4; r++) acc[j][r] = 0.f;

    for (int tile = 0; tile < CHUNK / P1TS; tile++) {
        const float* Kt = Kh + (size_t)tile * P1TS * DIM;
        const float* Vt = Vh + (size_t)tile * P1TS * DIM;
        __syncthreads();
        // ---- stage K (relu, fp16) and V (fp16): 1024 float4 each / 128 thr
#pragma unroll 4
        for (int l = 0; l < 8; l++) {
            int idx = l * 128 + tid;
            int s = idx >> 4;
            int c = (idx & 15) * 4;
            float4 kq = *(const float4*)(Kt + (size_t)s * DIM + c);
            kq.x = fmaxf(kq.x, 0.f); kq.y = fmaxf(kq.y, 0.f);
            kq.z = fmaxf(kq.z, 0.f); kq.w = fmaxf(kq.w, 0.f);
            *(uint2*)(Ks + (size_t)s * KSTR + c) =
                make_uint2(pack_h2(__float2half_rn(kq.x), __float2half_rn(kq.y)),
                           pack_h2(__float2half_rn(kq.z), __float2half_rn(kq.w)));
            float4 vq = *(const float4*)(Vt + (size_t)s * DIM + c);
            *(uint2*)(Vs + (size_t)s * VSTR + c) =
                make_uint2(pack_h2(__float2half_rn(vq.x), __float2half_rn(vq.y)),
                           pack_h2(__float2half_rn(vq.z), __float2half_rn(vq.w)));
        }
        // ones column block: cols [64..71] = {1,0,0,0,0,0,0,0} per row
        if (tid < P1TS) {
            __half* vrow = Vs + (size_t)tid * VSTR;
            *(uint4*)(vrow + 64) = make_uint4(0x3C00u, 0u, 0u, 0u);
        }
        __syncthreads();

        // ---- MMA: 4 k-steps x 9 n-tiles ----
#pragma unroll
        for (int ks = 0; ks < 4; ks++) {
            uint32_t a0, a1, a2, a3;
            asm volatile("ldmatrix.sync.aligned.m8n8.x4.trans.shared.b16 "
                         "{%0,%1,%2,%3}, [%4];"
                         : "=r"(a0), "=r"(a1), "=r"(a2), "=r"(a3)
                         : "r"(aAddr0 + (uint32_t)(ks * 16 * KSTR * 2)));
#pragma unroll
            for (int j = 0; j < 9; j++) {
                uint32_t b0, b1;
                asm volatile("ldmatrix.sync.aligned.m8n8.x2.trans.shared.b16 "
                             "{%0,%1}, [%2];"
                             : "=r"(b0), "=r"(b1)
                             : "r"(bAddr0 + (uint32_t)(ks * 16 * VSTR * 2 + j * 16)));
                asm volatile(
                    "mma.sync.aligned.m16n8k16.row.col.f32.f16.f16.f32 "
                    "{%0,%1,%2,%3}, {%4,%5,%6,%7}, {%8,%9}, {%0,%1,%2,%3};"
                    : "+f"(acc[j][0]), "+f"(acc[j][1]),
                      "+f"(acc[j][2]), "+f"(acc[j][3])
                    : "r"(a0), "r"(a1), "r"(a2), "r"(a3), "r"(b0), "r"(b1));
            }
        }
    }

    // ---- epilogue: cols 0-63 -> kv_part; col 64 -> ksum ----
    const int g = lane >> 2;
    const int c2 = (lane & 3) * 2;
    float* kvp = g_kv_part + ((size_t)bh * NCHUNK + chunk) * DIM * DIM;
#pragma unroll
    for (int j = 0; j < 8; j++) {
        *(float2*)(kvp + (size_t)(m0 + g) * DIM + j * 8 + c2) =
            make_float2(acc[j][0], acc[j][1]);
        *(float2*)(kvp + (size_t)(m0 + g + 8) * DIM + j * 8 + c2) =
            make_float2(acc[j][2], acc[j][3]);
    }
    if ((lane & 3) == 0) {
        float* ksp = g_ks_part + ((size_t)bh * NCHUNK + chunk) * DIM;
        ksp[m0 + g]     = acc[8][0];
        ksp[m0 + g + 8] = acc[8][2];
    }
}

// ---------------------------------------------------------------------------
// Reduce partials -> g_kvT[bh][72][64] (kv^T, ksum row 64, zero pad 65-71)
// ---------------------------------------------------------------------------
__global__ __launch_bounds__(256) void la_reduce() {
    const int bh  = blockIdx.x;
    const int tid = threadIdx.x;
    float* outT = g_kvT + (size_t)bh * 72 * DIM;
    for (int idx = tid; idx < DIM * DIM; idx += 256) {
        int d = idx >> 6, e = idx & 63;
        float sum = 0.f;
#pragma unroll
        for (int c = 0; c < NCHUNK; c++)
            sum += g_kv_part[((size_t)bh * NCHUNK + c) * DIM * DIM + idx];
        outT[e * DIM + d] = sum;
    }
    if (tid < DIM) {
        float s = 0.f;
#pragma unroll
        for (int c = 0; c < NCHUNK; c++)
            s += g_ks_part[((size_t)bh * NCHUNK + c) * DIM + tid];
        outT[64 * DIM + tid] = s;
    }
    for (int i = tid; i < 7 * DIM; i += 256)
        outT[65 * DIM + i] = 0.f;
}

// ===========================================================================
// Phase 2, pure fp16 HMMA, register-direct A fragments, 8 n-tiles.
// Normalizer on the fma pipe from the ALREADY-LOADED fp32 Q registers:
// per-lane dot(relu(Q frag), ksum frag from g_kvT row 64) + quad shfl-reduce.
// smem = B only (64 rows, 9.2 KB).
// ===========================================================================
#define KPADB 72
#define P2_SMEM (64 * KPADB * 2)    // 9216

__global__ __launch_bounds__(256) void la_phase2(const float* __restrict__ Q,
                                                 float* __restrict__ O) {
    extern __shared__ char sm[];
    __half* Bs = (__half*)sm;

    const int bh = blockIdx.x;
    const int rb = blockIdx.y;
    const float* Qh = Q + (size_t)bh * SEQ * DIM + (size_t)rb * 128 * DIM;

    const int tid  = threadIdx.x;
    const int lane = tid & 31;
    const int wid  = tid >> 5;
    const int m0   = wid * 16;
    const int g    = lane >> 2;
    const int c    = lane & 3;

    // ---- A fragments direct from gmem (16 float2 per thread, high MLP) ----
    const float* Qr0 = Qh + (size_t)(m0 + g) * DIM;
    const float* Qr8 = Qh + (size_t)(m0 + g + 8) * DIM;
    float2 x0[4], x2[4], y0[4], y2[4];
#pragma unroll
    for (int ks = 0; ks < 4; ks++) {
        x0[ks] = *(const float2*)(Qr0 + ks * 16 + 2 * c);
        x2[ks] = *(const float2*)(Qr0 + ks * 16 + 8 + 2 * c);
        y0[ks] = *(const float2*)(Qr8 + ks * 16 + 2 * c);
        y2[ks] = *(const float2*)(Qr8 + ks * 16 + 8 + 2 * c);
    }
    // relu in place (shared by MMA fragments and normalizer)
#pragma unroll
    for (int ks = 0; ks < 4; ks++) {
        x0[ks].x = fmaxf(x0[ks].x, 0.f); x0[ks].y = fmaxf(x0[ks].y, 0.f);
        x2[ks].x = fmaxf(x2[ks].x, 0.f); x2[ks].y = fmaxf(x2[ks].y, 0.f);
        y0[ks].x = fmaxf(y0[ks].x, 0.f); y0[ks].y = fmaxf(y0[ks].y, 0.f);
        y2[ks].x = fmaxf(y2[ks].x, 0.f); y2[ks].y = fmaxf(y2[ks].y, 0.f);
    }

    // ---- stage B = fp16(g_kvT rows 0-63): 1024 float4 / 256 thr = 4 each ----
    const float* Bg = g_kvT + (size_t)bh * 72 * DIM;
#pragma unroll
    for (int l = 0; l < 4; l++) {
        int idx = l * 256 + tid;
        int n = idx >> 4;
        int k = (idx & 15) * 4;
        float4 b = *(const float4*)(Bg + (size_t)n * DIM + k);
        *(uint2*)(Bs + (size_t)n * KPADB + k) =
            make_uint2(pack_h2(__float2half_rn(b.x), __float2half_rn(b.y)),
                       pack_h2(__float2half_rn(b.z), __float2half_rn(b.w)));
    }

    // ---- normalizer: dot fp32 Q-frags with ksum (g_kvT row 64, L2-hot) ----
    float ng = 0.f, nh = 0.f;
    {
        const float* ksr = Bg + 64 * DIM;
#pragma unroll
        for (int ks = 0; ks < 4; ks++) {
            float2 k0 = *(const float2*)(ksr + ks * 16 + 2 * c);
            float2 k2 = *(const float2*)(ksr + ks * 16 + 8 + 2 * c);
            ng += x0[ks].x * k0.x + x0[ks].y * k0.y
                + x2[ks].x * k2.x + x2[ks].y * k2.y;
            nh += y0[ks].x * k0.x + y0[ks].y * k0.y
                + y2[ks].x * k2.x + y2[ks].y * k2.y;
        }
        ng += __shfl_xor_sync(0xffffffffu, ng, 1);
        ng += __shfl_xor_sync(0xffffffffu, ng, 2);
        nh += __shfl_xor_sync(0xffffffffu, nh, 1);
        nh += __shfl_xor_sync(0xffffffffu, nh, 2);
    }

    // ---- convert A fragments ----
    uint32_t af[4][4];
#pragma unroll
    for (int ks = 0; ks < 4; ks++) {
        af[ks][0] = pack_h2(__float2half_rn(x0[ks].x), __float2half_rn(x0[ks].y));
        af[ks][1] = pack_h2(__float2half_rn(y0[ks].x), __float2half_rn(y0[ks].y));
        af[ks][2] = pack_h2(__float2half_rn(x2[ks].x), __float2half_rn(x2[ks].y));
        af[ks][3] = pack_h2(__float2half_rn(y2[ks].x), __float2half_rn(y2[ks].y));
    }
    __syncthreads();

    // ---- mainloop: 4 k-steps x 8 n-tiles ----
    uint32_t Bbase = (uint32_t)__cvta_generic_to_shared(Bs);
    uint32_t bAddr = Bbase + (uint32_t)(lane & 7) * (KPADB * 2)
                   + (uint32_t)((lane >> 3) & 1) * 16;

    float acc[8][4];
#pragma unroll
    for (int j = 0; j < 8; j++)
#pragma unroll
        for (int r = 0; r < 4; r++) acc[j][r] = 0.f;

#pragma unroll
    for (int ks = 0; ks < 4; ks++) {
#pragma unroll
        for (int j = 0; j < 8; j++) {
            uint32_t b0, b1;
            asm volatile("ldmatrix.sync.aligned.m8n8.x2.shared.b16 {%0,%1}, [%2];"
                         : "=r"(b0), "=r"(b1)
                         : "r"(bAddr + j * (8 * KPADB * 2) + ks * 32));
            asm volatile(
                "mma.sync.aligned.m16n8k16.row.col.f32.f16.f16.f32 "
                "{%0,%1,%2,%3}, {%4,%5,%6,%7}, {%8,%9}, {%0,%1,%2,%3};"
                : "+f"(acc[j][0]), "+f"(acc[j][1]), "+f"(acc[j][2]), "+f"(acc[j][3])
                : "r"(af[ks][0]), "r"(af[ks][1]), "r"(af[ks][2]), "r"(af[ks][3]),
                  "r"(b0), "r"(b1));
        }
    }

    // ---- epilogue ----
    float ilo = 1.f / fmaxf(ng, 1e-6f);
    float ihi = 1.f / fmaxf(nh, 1e-6f);

    float* O0 = O + ((size_t)bh * SEQ + (size_t)rb * 128 + m0 + g) * DIM + 2 * c;
    float* O1 = O0 + 8 * DIM;
#pragma unroll
    for (int j = 0; j < 8; j++) {
        *(float2*)(O0 + j * 8) = make_float2(acc[j][0] * ilo, acc[j][1] * ilo);
        *(float2*)(O1 + j * 8) = make_float2(acc[j][2] * ihi, acc[j][3] * ihi);
    }
}

// ---------------------------------------------------------------------------
extern "C" void kernel_launch(void* const* d_in, const int* in_sizes, int n_in,
                              void* d_out, int out_size) {
    const float* q = (const float*)d_in[0];
    const float* k = (const float*)d_in[1];
    const float* v = (const float*)d_in[2];
    float* o = (float*)d_out;

    static bool configured = false;
    if (!configured) {
        cudaFuncSetAttribute(la_phase1, cudaFuncAttributeMaxDynamicSharedMemorySize,
                             P1_SMEM);
        cudaFuncSetAttribute(la_phase2, cudaFuncAttributeMaxDynamicSharedMemorySize,
                             P2_SMEM);
        configured = true;
    }

    la_phase1<<<dim3(BH, NCHUNK), 128, P1_SMEM>>>(k, v);
    la_reduce<<<BH, 256>>>();
    la_phase2<<<dim3(BH, SEQ / 128), 256, P2_SMEM>>>(q, o);
}

// round 17
// speedup vs baseline: 2.4969x; 1.0700x over previous
#include <cuda_runtime.h>
#include <cuda_fp16.h>
#include <cstdint>

#define BH     64
#define SEQ    8192
#define DIM    64
#define NCHUNK 16
#define CHUNK  (SEQ / NCHUNK)   // 512
#define P1TS   64               // s rows per staged tile (8 tiles per chunk)

typedef unsigned long long u64;

// Scratch (allocation-free: __device__ globals)
__device__ float g_kv_part[BH * NCHUNK * DIM * DIM];  // 16 MB
__device__ float g_ks_part[BH * NCHUNK * DIM];
__device__ float g_kvT[BH * 72 * DIM];                // [e(64)+ksum(1)+pad(7)][d(64)]

__device__ __forceinline__ uint32_t pack_h2(__half a, __half b) {
    __half2 t = __halves2half2(a, b);
    return *(uint32_t*)&t;
}

// ===========================================================================
// Phase 1 (R15 measured-best config): pure fp16 HMMA + ones-column ksum.
// ===========================================================================
#define KSTR 72
#define VSTR 88
#define P1_K_BYTES (P1TS * KSTR * 2)      // 9216
#define P1_V_BYTES (P1TS * VSTR * 2)      // 11264
#define P1_SMEM (P1_K_BYTES + P1_V_BYTES) // 20480

__global__ __launch_bounds__(128) void la_phase1(const float* __restrict__ K,
                                                 const float* __restrict__ V) {
    extern __shared__ char sm1[];
    __half* Ks = (__half*)sm1;
    __half* Vs = (__half*)(sm1 + P1_K_BYTES);

    const int bh = blockIdx.x, chunk = blockIdx.y;
    const float* Kh = K + (size_t)bh * SEQ * DIM + (size_t)chunk * CHUNK * DIM;
    const float* Vh = V + (size_t)bh * SEQ * DIM + (size_t)chunk * CHUNK * DIM;

    const int tid  = threadIdx.x;
    const int lane = tid & 31;
    const int wid  = tid >> 5;
    const int m0   = wid * 16;        // d rows for this warp

    const int aRow = (lane & 7) + ((lane >> 4) << 3);
    const int aCol = m0 + (((lane >> 3) & 1) << 3);
    const int bRow = (lane & 7) + (((lane >> 3) & 1) << 3);

    uint32_t Kbase = (uint32_t)__cvta_generic_to_shared(Ks);
    uint32_t Vbase = (uint32_t)__cvta_generic_to_shared(Vs);
    uint32_t aAddr0 = Kbase + (uint32_t)(aRow * KSTR + aCol) * 2;
    uint32_t bAddr0 = Vbase + (uint32_t)(bRow * VSTR) * 2;

    float acc[9][4];
#pragma unroll
    for (int j = 0; j < 9; j++)
#pragma unroll
        for (int r = 0; r < 4; r++) acc[j][r] = 0.f;

    for (int tile = 0; tile < CHUNK / P1TS; tile++) {
        const float* Kt = Kh + (size_t)tile * P1TS * DIM;
        const float* Vt = Vh + (size_t)tile * P1TS * DIM;
        __syncthreads();
        // ---- stage K (relu, fp16) and V (fp16): 1024 float4 each / 128 thr
#pragma unroll 4
        for (int l = 0; l < 8; l++) {
            int idx = l * 128 + tid;
            int s = idx >> 4;
            int c = (idx & 15) * 4;
            float4 kq = *(const float4*)(Kt + (size_t)s * DIM + c);
            kq.x = fmaxf(kq.x, 0.f); kq.y = fmaxf(kq.y, 0.f);
            kq.z = fmaxf(kq.z, 0.f); kq.w = fmaxf(kq.w, 0.f);
            *(uint2*)(Ks + (size_t)s * KSTR + c) =
                make_uint2(pack_h2(__float2half_rn(kq.x), __float2half_rn(kq.y)),
                           pack_h2(__float2half_rn(kq.z), __float2half_rn(kq.w)));
            float4 vq = *(const float4*)(Vt + (size_t)s * DIM + c);
            *(uint2*)(Vs + (size_t)s * VSTR + c) =
                make_uint2(pack_h2(__float2half_rn(vq.x), __float2half_rn(vq.y)),
                           pack_h2(__float2half_rn(vq.z), __float2half_rn(vq.w)));
        }
        // ones column block: cols [64..71] = {1,0,0,0,0,0,0,0} per row
        if (tid < P1TS) {
            __half* vrow = Vs + (size_t)tid * VSTR;
            *(uint4*)(vrow + 64) = make_uint4(0x3C00u, 0u, 0u, 0u);
        }
        __syncthreads();

        // ---- MMA: 4 k-steps x 9 n-tiles ----
#pragma unroll
        for (int ks = 0; ks < 4; ks++) {
            uint32_t a0, a1, a2, a3;
            asm volatile("ldmatrix.sync.aligned.m8n8.x4.trans.shared.b16 "
                         "{%0,%1,%2,%3}, [%4];"
                         : "=r"(a0), "=r"(a1), "=r"(a2), "=r"(a3)
                         : "r"(aAddr0 + (uint32_t)(ks * 16 * KSTR * 2)));
#pragma unroll
            for (int j = 0; j < 9; j++) {
                uint32_t b0, b1;
                asm volatile("ldmatrix.sync.aligned.m8n8.x2.trans.shared.b16 "
                             "{%0,%1}, [%2];"
                             : "=r"(b0), "=r"(b1)
                             : "r"(bAddr0 + (uint32_t)(ks * 16 * VSTR * 2 + j * 16)));
                asm volatile(
                    "mma.sync.aligned.m16n8k16.row.col.f32.f16.f16.f32 "
                    "{%0,%1,%2,%3}, {%4,%5,%6,%7}, {%8,%9}, {%0,%1,%2,%3};"
                    : "+f"(acc[j][0]), "+f"(acc[j][1]),
                      "+f"(acc[j][2]), "+f"(acc[j][3])
                    : "r"(a0), "r"(a1), "r"(a2), "r"(a3), "r"(b0), "r"(b1));
            }
        }
    }

    // ---- epilogue: cols 0-63 -> kv_part; col 64 -> ksum ----
    const int g = lane >> 2;
    const int c2 = (lane & 3) * 2;
    float* kvp = g_kv_part + ((size_t)bh * NCHUNK + chunk) * DIM * DIM;
#pragma unroll
    for (int j = 0; j < 8; j++) {
        *(float2*)(kvp + (size_t)(m0 + g) * DIM + j * 8 + c2) =
            make_float2(acc[j][0], acc[j][1]);
        *(float2*)(kvp + (size_t)(m0 + g + 8) * DIM + j * 8 + c2) =
            make_float2(acc[j][2], acc[j][3]);
    }
    if ((lane & 3) == 0) {
        float* ksp = g_ks_part + ((size_t)bh * NCHUNK + chunk) * DIM;
        ksp[m0 + g]     = acc[8][0];
        ksp[m0 + g + 8] = acc[8][2];
    }
}

// ---------------------------------------------------------------------------
// Reduce partials -> g_kvT[bh][72][64] (kv^T, ksum row 64, zero pad 65-71)
// ---------------------------------------------------------------------------
__global__ __launch_bounds__(256) void la_reduce() {
    const int bh  = blockIdx.x;
    const int tid = threadIdx.x;
    float* outT = g_kvT + (size_t)bh * 72 * DIM;
    for (int idx = tid; idx < DIM * DIM; idx += 256) {
        int d = idx >> 6, e = idx & 63;
        float sum = 0.f;
#pragma unroll
        for (int c = 0; c < NCHUNK; c++)
            sum += g_kv_part[((size_t)bh * NCHUNK + c) * DIM * DIM + idx];
        outT[e * DIM + d] = sum;
    }
    if (tid < DIM) {
        float s = 0.f;
#pragma unroll
        for (int c = 0; c < NCHUNK; c++)
            s += g_ks_part[((size_t)bh * NCHUNK + c) * DIM + tid];
        outT[64 * DIM + tid] = s;
    }
    for (int i = tid; i < 7 * DIM; i += 256)
        outT[65 * DIM + i] = 0.f;
}

// ===========================================================================
// Phase 2, pipelined: RBLK row-blocks of 128 per CTA (grid 64 x 16).
// B staged ONCE; per block: convert cur A-frags -> issue next block's Q LDGs
// -> MMA -> epilogue. Next block's loads overlap current block's compute.
// Normalizer on fma pipe from fp32 Q regs (R16-proven).
// ===========================================================================
#define RBLK 4
#define KPADB 72
#define P2_SMEM (64 * KPADB * 2)    // 9216

__global__ __launch_bounds__(256, 2) void la_phase2(const float* __restrict__ Q,
                                                    float* __restrict__ O) {
    extern __shared__ char sm[];
    __half* Bs = (__half*)sm;

    const int bh  = blockIdx.x;
    const int rb0 = blockIdx.y * RBLK;
    const float* Qb = Q + (size_t)bh * SEQ * DIM + (size_t)rb0 * 128 * DIM;
    float* Ob       = O + (size_t)bh * SEQ * DIM + (size_t)rb0 * 128 * DIM;

    const int tid  = threadIdx.x;
    const int lane = tid & 31;
    const int wid  = tid >> 5;
    const int m0   = wid * 16;
    const int g    = lane >> 2;
    const int c    = lane & 3;

    const float* Qr0 = Qb + (size_t)(m0 + g) * DIM;
    const float* Qr8 = Qb + (size_t)(m0 + g + 8) * DIM;
    const float* Bg  = g_kvT + (size_t)bh * 72 * DIM;
    const float* ksr = Bg + 64 * DIM;

    // ---- stage B once: 1024 float4 / 256 thr = 4 each ----
#pragma unroll
    for (int l = 0; l < 4; l++) {
        int idx = l * 256 + tid;
        int n = idx >> 4;
        int k = (idx & 15) * 4;
        float4 b = *(const float4*)(Bg + (size_t)n * DIM + k);
        *(uint2*)(Bs + (size_t)n * KPADB + k) =
            make_uint2(pack_h2(__float2half_rn(b.x), __float2half_rn(b.y)),
                       pack_h2(__float2half_rn(b.z), __float2half_rn(b.w)));
    }

    // ---- load block 0's A fragments ----
    float2 cx0[4], cx2[4], cy0[4], cy2[4];
#pragma unroll
    for (int ks = 0; ks < 4; ks++) {
        cx0[ks] = *(const float2*)(Qr0 + ks * 16 + 2 * c);
        cx2[ks] = *(const float2*)(Qr0 + ks * 16 + 8 + 2 * c);
        cy0[ks] = *(const float2*)(Qr8 + ks * 16 + 2 * c);
        cy2[ks] = *(const float2*)(Qr8 + ks * 16 + 8 + 2 * c);
    }

    uint32_t Bbase = (uint32_t)__cvta_generic_to_shared(Bs);
    uint32_t bAddr = Bbase + (uint32_t)(lane & 7) * (KPADB * 2)
                   + (uint32_t)((lane >> 3) & 1) * 16;

    __syncthreads();   // B ready

#pragma unroll
    for (int r = 0; r < RBLK; r++) {
        // ---- relu + normalizer + convert current block (frees fp32 regs) ----
        float ng = 0.f, nh = 0.f;
        uint32_t af[4][4];
#pragma unroll
        for (int ks = 0; ks < 4; ks++) {
            float2 k0 = *(const float2*)(ksr + ks * 16 + 2 * c);
            float2 k2 = *(const float2*)(ksr + ks * 16 + 8 + 2 * c);
            cx0[ks].x = fmaxf(cx0[ks].x, 0.f); cx0[ks].y = fmaxf(cx0[ks].y, 0.f);
            cx2[ks].x = fmaxf(cx2[ks].x, 0.f); cx2[ks].y = fmaxf(cx2[ks].y, 0.f);
            cy0[ks].x = fmaxf(cy0[ks].x, 0.f); cy0[ks].y = fmaxf(cy0[ks].y, 0.f);
            cy2[ks].x = fmaxf(cy2[ks].x, 0.f); cy2[ks].y = fmaxf(cy2[ks].y, 0.f);
            ng += cx0[ks].x * k0.x + cx0[ks].y * k0.y
                + cx2[ks].x * k2.x + cx2[ks].y * k2.y;
            nh += cy0[ks].x * k0.x + cy0[ks].y * k0.y
                + cy2[ks].x * k2.x + cy2[ks].y * k2.y;
            af[ks][0] = pack_h2(__float2half_rn(cx0[ks].x), __float2half_rn(cx0[ks].y));
            af[ks][1] = pack_h2(__float2half_rn(cy0[ks].x), __float2half_rn(cy0[ks].y));
            af[ks][2] = pack_h2(__float2half_rn(cx2[ks].x), __float2half_rn(cx2[ks].y));
            af[ks][3] = pack_h2(__float2half_rn(cy2[ks].x), __float2half_rn(cy2[ks].y));
        }
        ng += __shfl_xor_sync(0xffffffffu, ng, 1);
        ng += __shfl_xor_sync(0xffffffffu, ng, 2);
        nh += __shfl_xor_sync(0xffffffffu, nh, 1);
        nh += __shfl_xor_sync(0xffffffffu, nh, 2);

        // ---- prefetch next block's A fragments (overlaps MMA below) ----
        if (r + 1 < RBLK) {
            const float* Pr0 = Qr0 + (size_t)(r + 1) * 128 * DIM;
            const float* Pr8 = Qr8 + (size_t)(r + 1) * 128 * DIM;
#pragma unroll
            for (int ks = 0; ks < 4; ks++) {
                cx0[ks] = *(const float2*)(Pr0 + ks * 16 + 2 * c);
                cx2[ks] = *(const float2*)(Pr0 + ks * 16 + 8 + 2 * c);
                cy0[ks] = *(const float2*)(Pr8 + ks * 16 + 2 * c);
                cy2[ks] = *(const float2*)(Pr8 + ks * 16 + 8 + 2 * c);
            }
        }

        // ---- MMA: 4 k-steps x 8 n-tiles ----
        float acc[8][4];
#pragma unroll
        for (int j = 0; j < 8; j++)
#pragma unroll
            for (int q = 0; q < 4; q++) acc[j][q] = 0.f;

#pragma unroll
        for (int ks = 0; ks < 4; ks++) {
#pragma unroll
            for (int j = 0; j < 8; j++) {
                uint32_t b0, b1;
                asm volatile("ldmatrix.sync.aligned.m8n8.x2.shared.b16 {%0,%1}, [%2];"
                             : "=r"(b0), "=r"(b1)
                             : "r"(bAddr + j * (8 * KPADB * 2) + ks * 32));
                asm volatile(
                    "mma.sync.aligned.m16n8k16.row.col.f32.f16.f16.f32 "
                    "{%0,%1,%2,%3}, {%4,%5,%6,%7}, {%8,%9}, {%0,%1,%2,%3};"
                    : "+f"(acc[j][0]), "+f"(acc[j][1]),
                      "+f"(acc[j][2]), "+f"(acc[j][3])
                    : "r"(af[ks][0]), "r"(af[ks][1]), "r"(af[ks][2]), "r"(af[ks][3]),
                      "r"(b0), "r"(b1));
            }
        }

        // ---- epilogue for block r ----
        float ilo = 1.f / fmaxf(ng, 1e-6f);
        float ihi = 1.f / fmaxf(nh, 1e-6f);
        float* O0 = Ob + (size_t)(r * 128 + m0 + g) * DIM + 2 * c;
        float* O1 = O0 + 8 * DIM;
#pragma unroll
        for (int j = 0; j < 8; j++) {
            *(float2*)(O0 + j * 8) = make_float2(acc[j][0] * ilo, acc[j][1] * ilo);
            *(float2*)(O1 + j * 8) = make_float2(acc[j][2] * ihi, acc[j][3] * ihi);
        }
    }
}

// ---------------------------------------------------------------------------
extern "C" void kernel_launch(void* const* d_in, const int* in_sizes, int n_in,
                              void* d_out, int out_size) {
    const float* q = (const float*)d_in[0];
    const float* k = (const float*)d_in[1];
    const float* v = (const float*)d_in[2];
    float* o = (float*)d_out;

    static bool configured = false;
    if (!configured) {
        cudaFuncSetAttribute(la_phase1, cudaFuncAttributeMaxDynamicSharedMemorySize,
                             P1_SMEM);
        cudaFuncSetAttribute(la_phase2, cudaFuncAttributeMaxDynamicSharedMemorySize,
                             P2_SMEM);
        configured = true;
    }

    la_phase1<<<dim3(BH, NCHUNK), 128, P1_SMEM>>>(k, v);
    la_reduce<<<BH, 256>>>();
    la_phase2<<<dim3(BH, SEQ / (128 * RBLK)), 256, P2_SMEM>>>(q, o);
}